// round 2
// baseline (speedup 1.0000x reference)
#include <cuda_runtime.h>
#include <math.h>

#define NBLK 128
#define NTH  256
#define RPB  64
#define AP   101
#define HPP  113
#define ZP   101
#define WP   112
#define SMEM_BYTES (40032*4)

__device__ float g_sum[63][4][128];
__device__ float g_ss2[63][4][128];
__device__ unsigned g_cnt = 0;
__device__ unsigned g_gen = 0;

__device__ __forceinline__ void gridbar() {
    __threadfence();
    __syncthreads();
    if (threadIdx.x == 0) {
        volatile unsigned* vg = (volatile unsigned*)&g_gen;
        unsigned gen = *vg;
        if (atomicAdd(&g_cnt, 1u) == NBLK - 1u) {
            atomicExch(&g_cnt, 0u);
            __threadfence();
            atomicAdd(&g_gen, 1u);
        } else {
            while (*vg == gen) { __nanosleep(64); }
        }
        __threadfence();
    }
    __syncthreads();
}

// accurate sin, immune to fast-math: double-precision range reduction
__device__ __forceinline__ float my_sin(float x) {
    double xd = (double)x;
    double kd = rint(xd * 0.6366197723675814);
    int k = (int)kd;
    float r = (float)(xd - kd * 1.5707963267948966);
    float r2 = r * r;
    float sp = fmaf(r2, 2.7557314e-6f, -1.9841270e-4f);
    sp = fmaf(r2, sp, 8.3333331e-3f);
    sp = fmaf(r2, sp, -1.6666667e-1f);
    sp = r * fmaf(r2, sp, 1.0f);
    float cp = fmaf(r2, 2.4801587e-5f, -1.3888889e-3f);
    cp = fmaf(r2, cp, 4.1666666e-2f);
    cp = fmaf(r2, cp, -0.5f);
    cp = fmaf(r2, cp, 1.0f);
    int kk = k & 3;
    float res = (kk & 1) ? cp : sp;
    if (kk >= 2) res = -res;
    return res;
}

__device__ __forceinline__ void make_affine(const float* gs, const float* gq,
                                            const float* __restrict__ gamma,
                                            const float* __restrict__ beta,
                                            int nf, float* affA, float* affC) {
    int f = threadIdx.x;
    if (f < nf) {
        float mu  = __ldcg(&gs[f]) * (1.f / 8192.f);
        float ex2 = __ldcg(&gq[f]) * (1.f / 8192.f);
        float v = fmaxf(ex2 - mu * mu, 0.f) + 1e-6f;
        float rs = rsqrtf(v);
        rs = rs * (1.5f - 0.5f * v * rs * rs);   // Newton refine
        float a = gamma[f] * rs;
        affA[f] = a;
        affC[f] = fmaf(-a, mu, beta[f]);
    }
}

__device__ __forceinline__ void accum_stats(const float* buf, int pitch, int nf,
                                            float* gs, float* gq) {
    int f = threadIdx.x & 127;
    int rh = threadIdx.x >> 7;       // 0 or 1 -> rows [0,32) / [32,64)
    if (f < nf) {
        float s1 = 0.f, s2 = 0.f;
        const float* p = buf + rh * 32 * pitch + f;
#pragma unroll 8
        for (int r = 0; r < 32; r++) { float v = p[r * pitch]; s1 += v; s2 = fmaf(v, v, s2); }
        atomicAdd(&gs[f], s1);
        atomicAdd(&gq[f], s2);
    }
}

template<int K, int NC>
__device__ __forceinline__ void gemm64(const float* __restrict__ A,
                                       const float* __restrict__ wmat,
                                       float* __restrict__ dst, int dp) {
    int rg = threadIdx.x >> 4, cg = threadIdx.x & 15;
    int r0 = rg * 4, j0 = cg * 7;
    float acc[4][7];
#pragma unroll
    for (int i = 0; i < 4; i++)
#pragma unroll
        for (int u = 0; u < 7; u++) acc[i][u] = 0.f;
    const float* a0 = A + r0 * HPP;
    const float* wp = wmat + j0;
#pragma unroll 4
    for (int k = 0; k < K; k++) {
        float x0 = a0[k], x1 = a0[HPP + k], x2 = a0[2 * HPP + k], x3 = a0[3 * HPP + k];
        const float* wr = wp + k * WP;
#pragma unroll
        for (int u = 0; u < 7; u++) {
            float wv = wr[u];
            acc[0][u] = fmaf(x0, wv, acc[0][u]);
            acc[1][u] = fmaf(x1, wv, acc[1][u]);
            acc[2][u] = fmaf(x2, wv, acc[2][u]);
            acc[3][u] = fmaf(x3, wv, acc[3][u]);
        }
    }
#pragma unroll
    for (int u = 0; u < 7; u++) {
        int j = j0 + u;
        if (j < NC) {
#pragma unroll
            for (int i = 0; i < 4; i++) dst[(r0 + i) * dp + j] = acc[i][u];
        }
    }
}

__global__ void __launch_bounds__(NTH, 1)
fullnn(const float* __restrict__ W,
       const float* __restrict__ y_init, const float* __restrict__ z_init,
       const float* __restrict__ g0, const float* __restrict__ b0,
       const float* __restrict__ g1, const float* __restrict__ b1,
       const float* __restrict__ g2, const float* __restrict__ b2,
       const float* __restrict__ g3, const float* __restrict__ b3,
       const float* __restrict__ w0, const float* __restrict__ w1,
       const float* __restrict__ w2,
       float* __restrict__ out)
{
    extern __shared__ float sm[];
    float* xs   = sm;                        // 64*101
    float* ys   = xs + RPB * AP;             // 64
    float* zr   = ys + RPB;                  // 64*101
    float* hA   = zr + RPB * ZP;             // 64*113
    float* hB   = hA + RPB * HPP;            // 64*113
    float* wb   = hB + RPB * HPP;            // 110*112
    float* affA = wb + 110 * WP;             // 128
    float* affC = affA + 128;                // 128

    const int tid  = threadIdx.x;
    const int bk   = blockIdx.x;
    const int row0 = bk * RPB;
    const int r_ = tid >> 2, q_ = tid & 3;

    // zero global stats
    {
        float* p1 = &g_sum[0][0][0];
        float* p2 = &g_ss2[0][0][0];
        for (int i = bk * NTH + tid; i < 63 * 4 * 128; i += NBLK * NTH) { p1[i] = 0.f; p2[i] = 0.f; }
    }
    const float y0v = y_init[0];
    const float z0v = z_init[0];
    for (int i = tid; i < RPB * 100; i += NTH) {
        int r = i / 100, d = i % 100;
        xs[r * AP + d] = 1.57079632679489662f;
    }
    for (int r = tid; r < RPB; r += NTH) ys[r] = y0v;
    gridbar();

    for (int s = 0; s < 63; s++) {
        // ---- Phase A: BN3 affine (prev step), x/y update, build h, stats0
        if (s > 0)
            make_affine(g_sum[s-1][3], g_ss2[s-1][3], g3 + (s-1)*100, b3 + (s-1)*100, 100, affA, affC);
        __syncthreads();
        {
            float ec = expf(-0.3f * (1.0f - (float)s * (1.0f / 64.0f)));
            float yold = ys[r_];
            const float* Wr = W + ((size_t)(row0 + r_) * 64 + s) * 100;
            float ssin = 0.f, zdot = 0.f;
            for (int d = q_; d < 100; d += 4) {
                float dw = Wr[100 + d] - Wr[d];
                float xn = fmaf(0.3f * dw, yold, xs[r_ * AP + d]);
                xs[r_ * AP + d] = xn;
                hA[r_ * HPP + d] = xn;
                ssin += my_sin(xn);
                float zv = (s == 0) ? z0v : fmaf(affA[d], zr[r_ * ZP + d], affC[d]) * 0.01f;
                zdot = fmaf(zv, dw, zdot);
            }
            ssin += __shfl_xor_sync(0xffffffffu, ssin, 1);
            ssin += __shfl_xor_sync(0xffffffffu, ssin, 2);
            zdot += __shfl_xor_sync(0xffffffffu, zdot, 1);
            zdot += __shfl_xor_sync(0xffffffffu, zdot, 2);
            if (q_ == 0) {
                float tc = 0.1f * ssin;
                float dr = fmaf(-0.1f, yold, 0.045f * ec * tc * tc * tc);
                float yn = yold - dr * (1.0f / 64.0f) + zdot;
                ys[r_] = yn;
                hA[r_ * HPP + 100] = yn;
            }
        }
        __syncthreads();
        accum_stats(hA, HPP, 101, g_sum[s][0], g_ss2[s][0]);
        gridbar();

        // ---- Phase B: BN0, GEMM0, stats1
        make_affine(g_sum[s][0], g_ss2[s][0], g0 + s*101, b0 + s*101, 101, affA, affC);
        {
            const float* ws = w0 + (size_t)s * 101 * 110;
            for (int i = tid; i < 101 * 110; i += NTH) wb[(i / 110) * WP + (i % 110)] = ws[i];
        }
        __syncthreads();
        for (int i = tid; i < RPB * 101; i += NTH) {
            int r = i / 101, f = i % 101;
            hA[r * HPP + f] = fmaf(affA[f], hA[r * HPP + f], affC[f]);
        }
        __syncthreads();
        gemm64<101, 110>(hA, wb, hB, HPP);
        __syncthreads();
        accum_stats(hB, HPP, 110, g_sum[s][1], g_ss2[s][1]);
        gridbar();

        // ---- Phase C: BN1+relu, GEMM1, stats2
        make_affine(g_sum[s][1], g_ss2[s][1], g1 + s*110, b1 + s*110, 110, affA, affC);
        {
            const float* ws = w1 + (size_t)s * 110 * 110;
            for (int i = tid; i < 110 * 110; i += NTH) wb[(i / 110) * WP + (i % 110)] = ws[i];
        }
        __syncthreads();
        for (int i = tid; i < RPB * 110; i += NTH) {
            int r = i / 110, f = i % 110;
            hA[r * HPP + f] = fmaxf(fmaf(affA[f], hB[r * HPP + f], affC[f]), 0.f);
        }
        __syncthreads();
        gemm64<110, 110>(hA, wb, hB, HPP);
        __syncthreads();
        accum_stats(hB, HPP, 110, g_sum[s][2], g_ss2[s][2]);
        gridbar();

        // ---- Phase D: BN2+relu, GEMM2 -> zr (raw), stats3  (bias2 cancels in BN3)
        make_affine(g_sum[s][2], g_ss2[s][2], g2 + s*110, b2 + s*110, 110, affA, affC);
        {
            const float* ws = w2 + (size_t)s * 110 * 100;
            for (int i = tid; i < 110 * 100; i += NTH) wb[(i / 100) * WP + (i % 100)] = ws[i];
        }
        __syncthreads();
        for (int i = tid; i < RPB * 110; i += NTH) {
            int r = i / 110, f = i % 110;
            hA[r * HPP + f] = fmaxf(fmaf(affA[f], hB[r * HPP + f], affC[f]), 0.f);
        }
        __syncthreads();
        gemm64<110, 100>(hA, wb, zr, ZP);
        __syncthreads();
        accum_stats(zr, ZP, 100, g_sum[s][3], g_ss2[s][3]);
        gridbar();
    }

    // ---- Final extra step (reuses dW[62], ec[62]); write outputs
    make_affine(g_sum[62][3], g_ss2[62][3], g3 + 62*100, b3 + 62*100, 100, affA, affC);
    __syncthreads();
    {
        float ec = expf(-0.3f * (1.0f - 62.0f / 64.0f));
        float yold = ys[r_];
        const float* Wr = W + ((size_t)(row0 + r_) * 64 + 62) * 100;
        float ssin = 0.f, zdot = 0.f;
        for (int d = q_; d < 100; d += 4) {
            float dw = Wr[100 + d] - Wr[d];
            float xn = fmaf(0.3f * dw, yold, xs[r_ * AP + d]);
            out[(size_t)(row0 + r_) * 100 + d] = xn;
            ssin += my_sin(xn);
            float zv = fmaf(affA[d], zr[r_ * ZP + d], affC[d]) * 0.01f;
            zdot = fmaf(zv, dw, zdot);
        }
        ssin += __shfl_xor_sync(0xffffffffu, ssin, 1);
        ssin += __shfl_xor_sync(0xffffffffu, ssin, 2);
        zdot += __shfl_xor_sync(0xffffffffu, zdot, 1);
        zdot += __shfl_xor_sync(0xffffffffu, zdot, 2);
        if (q_ == 0) {
            float tc = 0.1f * ssin;
            float dr = fmaf(-0.1f, yold, 0.045f * ec * tc * tc * tc);
            out[(size_t)8192 * 100 + row0 + r_] = yold - dr * (1.0f / 64.0f) + zdot;
        }
    }
}

extern "C" void kernel_launch(void* const* d_in, const int* in_sizes, int n_in,
                              void* d_out, int out_size) {
    cudaFuncSetAttribute(fullnn, cudaFuncAttributeMaxDynamicSharedMemorySize, SMEM_BYTES);
    fullnn<<<NBLK, NTH, SMEM_BYTES>>>(
        (const float*)d_in[0], (const float*)d_in[1], (const float*)d_in[2],
        (const float*)d_in[3], (const float*)d_in[4], (const float*)d_in[5],
        (const float*)d_in[6], (const float*)d_in[7], (const float*)d_in[8],
        (const float*)d_in[9], (const float*)d_in[10], (const float*)d_in[11],
        (const float*)d_in[12], (const float*)d_in[13],
        (float*)d_out);
}

// round 4
// speedup vs baseline: 1.0880x; 1.0880x over previous
#include <cuda_runtime.h>
#include <math.h>

#define NBLK 128
#define NTH  512
#define RPB  64
#define XP   104          // xs pitch
#define HP   120          // hA/hB pitch
#define FS   33           // stats padding stride (spread LTS slices)
#define WSTR 6400         // W cache slice stride (64*100 floats)

// smem layout (floats)
#define OFF_XS   0
#define OFF_YS   6656
#define OFF_HA   6720
#define OFF_HB   14400
#define OFF_WB   22080
#define OFF_AFA  34180
#define OFF_AFC  34308
#define OFF_WC   34436
#define SMEM_FLOATS 47236
#define SMEM_BYTES  (SMEM_FLOATS * 4)

__device__ __align__(16) float g_sum[63][4][128 * FS];
__device__ __align__(16) float g_ss2[63][4][128 * FS];
__device__ unsigned g_cnt = 0;
__device__ unsigned g_gen = 0;

__device__ __forceinline__ void gridbar() {
    __syncthreads();
    if (threadIdx.x == 0) {
        __threadfence();
        volatile unsigned* vg = (volatile unsigned*)&g_gen;
        unsigned gen = *vg;
        if (atomicAdd(&g_cnt, 1u) == NBLK - 1u) {
            *(volatile unsigned*)&g_cnt = 0u;
            __threadfence();
            atomicAdd(&g_gen, 1u);
        } else {
            while (*vg == gen) {}
        }
        __threadfence();
    }
    __syncthreads();
}

__device__ __forceinline__ void cp_async16(float* dst_smem, const float* src) {
    unsigned d = (unsigned)__cvta_generic_to_shared(dst_smem);
    asm volatile("cp.async.cg.shared.global [%0], [%1], 16;\n" :: "r"(d), "l"(src));
}
__device__ __forceinline__ void cp_commit() { asm volatile("cp.async.commit_group;\n"); }
__device__ __forceinline__ void cp_wait0()  { asm volatile("cp.async.wait_group 0;\n" ::: "memory"); }

// accurate sin, immune to fast-math: double-precision range reduction
__device__ __forceinline__ float my_sin(float x) {
    double xd = (double)x;
    double kd = rint(xd * 0.6366197723675814);
    int k = (int)kd;
    float r = (float)(xd - kd * 1.5707963267948966);
    float r2 = r * r;
    float sp = fmaf(r2, 2.7557314e-6f, -1.9841270e-4f);
    sp = fmaf(r2, sp, 8.3333331e-3f);
    sp = fmaf(r2, sp, -1.6666667e-1f);
    sp = r * fmaf(r2, sp, 1.0f);
    float cp = fmaf(r2, 2.4801587e-5f, -1.3888889e-3f);
    cp = fmaf(r2, cp, 4.1666666e-2f);
    cp = fmaf(r2, cp, -0.5f);
    cp = fmaf(r2, cp, 1.0f);
    int kk = k & 3;
    float res = (kk & 1) ? cp : sp;
    if (kk >= 2) res = -res;
    return res;
}

__device__ __forceinline__ void make_affine(const float* gs, const float* gq,
                                            const float* __restrict__ gamma,
                                            const float* __restrict__ beta,
                                            int nf, float* affA, float* affC) {
    int f = threadIdx.x;
    if (f < nf) {
        float mu  = __ldcg(&gs[f * FS]) * (1.f / 8192.f);
        float ex2 = __ldcg(&gq[f * FS]) * (1.f / 8192.f);
        float v = fmaxf(ex2 - mu * mu, 0.f) + 1e-6f;
        float rs = rsqrtf(v);
        rs = rs * (1.5f - 0.5f * v * rs * rs);
        float a = gamma[f] * rs;
        affA[f] = a;
        affC[f] = fmaf(-a, mu, beta[f]);
    }
}

__device__ __forceinline__ void accum_stats(const float* buf, int nf,
                                            float* gs, float* gq) {
    int f = threadIdx.x & 127;
    int q = threadIdx.x >> 7;        // 0..3 -> 16 rows each
    if (f < nf) {
        float s1 = 0.f, s2 = 0.f;
        const float* p = buf + q * 16 * HP + f;
#pragma unroll
        for (int r = 0; r < 16; r++) { float v = p[r * HP]; s1 += v; s2 = fmaf(v, v, s2); }
        atomicAdd(&gs[f * FS], s1);
        atomicAdd(&gq[f * FS], s2);
    }
}

// 64 x NC = 64 x K @ K x NC ; A pitch HP, weights linear pitch NC, dst pitch HP
// only threads < 256 participate (4x7 register tile)
template<int K, int NC>
__device__ __forceinline__ void gemm64(const float* __restrict__ A,
                                       const float* __restrict__ wm,
                                       float* __restrict__ dst) {
    if (threadIdx.x >= 256) return;
    int rg = threadIdx.x >> 4, cg = threadIdx.x & 15;
    int r0 = rg * 4, j0 = cg * 7;
    float acc[4][7];
#pragma unroll
    for (int i = 0; i < 4; i++)
#pragma unroll
        for (int u = 0; u < 7; u++) acc[i][u] = 0.f;
    const float* a0 = A + r0 * HP;
    const float* wp = wm + j0;
#pragma unroll 4
    for (int k = 0; k < K; k++) {
        float x0 = a0[k], x1 = a0[HP + k], x2 = a0[2 * HP + k], x3 = a0[3 * HP + k];
        const float* wr = wp + k * NC;
#pragma unroll
        for (int u = 0; u < 7; u++) {
            float wv = wr[u];
            acc[0][u] = fmaf(x0, wv, acc[0][u]);
            acc[1][u] = fmaf(x1, wv, acc[1][u]);
            acc[2][u] = fmaf(x2, wv, acc[2][u]);
            acc[3][u] = fmaf(x3, wv, acc[3][u]);
        }
    }
#pragma unroll
    for (int u = 0; u < 7; u++) {
        int j = j0 + u;
        if (j < NC) {
#pragma unroll
            for (int i = 0; i < 4; i++) dst[(r0 + i) * HP + j] = acc[i][u];
        }
    }
}

__device__ __forceinline__ void prefetch_W(float* Wcbuf, const float* W, int row0, int t) {
    for (int i = threadIdx.x; i < RPB * 25; i += NTH) {
        int r = i / 25, c = i % 25;
        cp_async16(Wcbuf + r * 100 + c * 4,
                   W + ((size_t)(row0 + r) * 64 + t) * 100 + c * 4);
    }
    cp_commit();
}

__global__ void __launch_bounds__(NTH, 1)
fullnn(const float* __restrict__ W,
       const float* __restrict__ y_init, const float* __restrict__ z_init,
       const float* __restrict__ g0, const float* __restrict__ b0,
       const float* __restrict__ g1, const float* __restrict__ b1,
       const float* __restrict__ g2, const float* __restrict__ b2,
       const float* __restrict__ g3, const float* __restrict__ b3,
       const float* __restrict__ w0, const float* __restrict__ w1,
       const float* __restrict__ w2,
       float* __restrict__ out)
{
    extern __shared__ float sm[];
    float* xs   = sm + OFF_XS;
    float* ys   = sm + OFF_YS;
    float* hA   = sm + OFF_HA;
    float* hB   = sm + OFF_HB;
    float* wb   = sm + OFF_WB;
    float* affA = sm + OFF_AFA;
    float* affC = sm + OFF_AFC;
    float* Wc   = sm + OFF_WC;    // 2 slices of WSTR floats

    const int tid  = threadIdx.x;
    const int bk   = blockIdx.x;
    const int row0 = bk * RPB;
    const int r_ = tid >> 3, q_ = tid & 7;

    // prefetch W[0], W[1]
    prefetch_W(Wc,        W, row0, 0);
    prefetch_W(Wc + WSTR, W, row0, 1);

    // zero stats (float4)
    {
        float4* p1 = (float4*)&g_sum[0][0][0];
        float4* p2 = (float4*)&g_ss2[0][0][0];
        int n4 = 63 * 4 * 128 * FS / 4;
        for (int i = bk * NTH + tid; i < n4; i += NBLK * NTH) {
            p1[i] = make_float4(0.f, 0.f, 0.f, 0.f);
            p2[i] = make_float4(0.f, 0.f, 0.f, 0.f);
        }
    }
    const float y0v = y_init[0];
    const float z0v = z_init[0];
    for (int i = tid; i < RPB * 100; i += NTH) {
        int r = i / 100, d = i % 100;
        xs[r * XP + d] = 1.57079632679489662f;
    }
    for (int r = tid; r < RPB; r += NTH) ys[r] = y0v;
    cp_wait0();
    gridbar();

    for (int s = 0; s < 63; s++) {
        // ---- Phase A: BN3 affine (prev), x/y update -> hA, stats0, stage w0
        cp_wait0();   // W[s+1] ready
        if (s > 0)
            make_affine(g_sum[s-1][3], g_ss2[s-1][3], g3 + (s-1)*100, b3 + (s-1)*100, 100, affA, affC);
        __syncthreads();
        {
            float ec = expf(-0.3f * (1.0f - (float)s * (1.0f / 64.0f)));
            float yold = ys[r_];
            const float* Wold = Wc + (s & 1) * WSTR + r_ * 100;
            const float* Wnew = Wc + ((s + 1) & 1) * WSTR + r_ * 100;
            float ssin = 0.f, zdot = 0.f;
            for (int d = q_; d < 100; d += 8) {
                float dw = Wnew[d] - Wold[d];
                float xn = fmaf(0.3f * dw, yold, xs[r_ * XP + d]);
                xs[r_ * XP + d] = xn;
                hA[r_ * HP + d] = xn;
                ssin += my_sin(xn);
                float zv = (s == 0) ? z0v : fmaf(affA[d], hB[r_ * HP + d], affC[d]) * 0.01f;
                zdot = fmaf(zv, dw, zdot);
            }
            ssin += __shfl_xor_sync(0xffffffffu, ssin, 1);
            ssin += __shfl_xor_sync(0xffffffffu, ssin, 2);
            ssin += __shfl_xor_sync(0xffffffffu, ssin, 4);
            zdot += __shfl_xor_sync(0xffffffffu, zdot, 1);
            zdot += __shfl_xor_sync(0xffffffffu, zdot, 2);
            zdot += __shfl_xor_sync(0xffffffffu, zdot, 4);
            if (q_ == 0) {
                float tc = 0.1f * ssin;
                float dr = fmaf(-0.1f, yold, 0.045f * ec * tc * tc * tc);
                float yn = yold - dr * (1.0f / 64.0f) + zdot;
                ys[r_] = yn;
                hA[r_ * HP + 100] = yn;
            }
        }
        __syncthreads();
        accum_stats(hA, 101, g_sum[s][0], g_ss2[s][0]);
        {   // stage w0 (float2, 11110 floats)
            const float2* src = (const float2*)(w0 + (size_t)s * 11110);
            float2* dst = (float2*)wb;
            for (int i = tid; i < 5555; i += NTH) dst[i] = src[i];
        }
        gridbar();

        // ---- Phase B: BN0, GEMM0, stats1, stage w1
        make_affine(g_sum[s][0], g_ss2[s][0], g0 + s*101, b0 + s*101, 101, affA, affC);
        __syncthreads();
        for (int i = tid; i < RPB * 101; i += NTH) {
            int r = i / 101, f = i % 101;
            hA[r * HP + f] = fmaf(affA[f], hA[r * HP + f], affC[f]);
        }
        __syncthreads();
        gemm64<101, 110>(hA, wb, hB);
        __syncthreads();
        accum_stats(hB, 110, g_sum[s][1], g_ss2[s][1]);
        {   // stage w1 (float4, 12100 floats)
            const float4* src = (const float4*)(w1 + (size_t)s * 12100);
            float4* dst = (float4*)wb;
            for (int i = tid; i < 3025; i += NTH) dst[i] = src[i];
        }
        gridbar();

        // ---- Phase C: BN1+relu, GEMM1, stats2, stage w2
        make_affine(g_sum[s][1], g_ss2[s][1], g1 + s*110, b1 + s*110, 110, affA, affC);
        __syncthreads();
        for (int i = tid; i < RPB * 110; i += NTH) {
            int r = i / 110, f = i % 110;
            hA[r * HP + f] = fmaxf(fmaf(affA[f], hB[r * HP + f], affC[f]), 0.f);
        }
        __syncthreads();
        gemm64<110, 110>(hA, wb, hB);
        __syncthreads();
        accum_stats(hB, 110, g_sum[s][2], g_ss2[s][2]);
        {   // stage w2 (float4, 11000 floats)
            const float4* src = (const float4*)(w2 + (size_t)s * 11000);
            float4* dst = (float4*)wb;
            for (int i = tid; i < 2750; i += NTH) dst[i] = src[i];
        }
        gridbar();

        // ---- Phase D: BN2+relu, prefetch W[s+2], GEMM2 -> hB (z raw), stats3
        make_affine(g_sum[s][2], g_ss2[s][2], g2 + s*110, b2 + s*110, 110, affA, affC);
        __syncthreads();
        for (int i = tid; i < RPB * 110; i += NTH) {
            int r = i / 110, f = i % 110;
            hA[r * HP + f] = fmaxf(fmaf(affA[f], hB[r * HP + f], affC[f]), 0.f);
        }
        __syncthreads();
        if (s <= 61) prefetch_W(Wc + (s & 1) * WSTR, W, row0, s + 2);
        gemm64<110, 100>(hA, wb, hB);
        __syncthreads();
        accum_stats(hB, 100, g_sum[s][3], g_ss2[s][3]);
        gridbar();
    }

    // ---- Final extra step (reuses dW[62]); write outputs
    make_affine(g_sum[62][3], g_ss2[62][3], g3 + 62*100, b3 + 62*100, 100, affA, affC);
    __syncthreads();
    {
        float ec = expf(-0.3f * (1.0f - 62.0f / 64.0f));
        float yold = ys[r_];
        const float* Wold = Wc + r_ * 100;           // slice0 = W[62]
        const float* Wnew = Wc + WSTR + r_ * 100;    // slice1 = W[63]
        float ssin = 0.f, zdot = 0.f;
        for (int d = q_; d < 100; d += 8) {
            float dw = Wnew[d] - Wold[d];
            float xn = fmaf(0.3f * dw, yold, xs[r_ * XP + d]);
            out[(size_t)(row0 + r_) * 100 + d] = xn;
            ssin += my_sin(xn);
            float zv = fmaf(affA[d], hB[r_ * HP + d], affC[d]) * 0.01f;
            zdot = fmaf(zv, dw, zdot);
        }
        ssin += __shfl_xor_sync(0xffffffffu, ssin, 1);
        ssin += __shfl_xor_sync(0xffffffffu, ssin, 2);
        ssin += __shfl_xor_sync(0xffffffffu, ssin, 4);
        zdot += __shfl_xor_sync(0xffffffffu, zdot, 1);
        zdot += __shfl_xor_sync(0xffffffffu, zdot, 2);
        zdot += __shfl_xor_sync(0xffffffffu, zdot, 4);
        if (q_ == 0) {
            float tc = 0.1f * ssin;
            float dr = fmaf(-0.1f, yold, 0.045f * ec * tc * tc * tc);
            out[(size_t)8192 * 100 + row0 + r_] = yold - dr * (1.0f / 64.0f) + zdot;
        }
    }
}

extern "C" void kernel_launch(void* const* d_in, const int* in_sizes, int n_in,
                              void* d_out, int out_size) {
    cudaFuncSetAttribute(fullnn, cudaFuncAttributeMaxDynamicSharedMemorySize, SMEM_BYTES);
    fullnn<<<NBLK, NTH, SMEM_BYTES>>>(
        (const float*)d_in[0], (const float*)d_in[1], (const float*)d_in[2],
        (const float*)d_in[3], (const float*)d_in[4], (const float*)d_in[5],
        (const float*)d_in[6], (const float*)d_in[7], (const float*)d_in[8],
        (const float*)d_in[9], (const float*)d_in[10], (const float*)d_in[11],
        (const float*)d_in[12], (const float*)d_in[13],
        (float*)d_out);
}

// round 5
// speedup vs baseline: 1.2240x; 1.1250x over previous
#include <cuda_runtime.h>
#include <math.h>

#define NBLK 128
#define NTH  512
#define RPB  64
#define XP   104
#define HP   120
#define FS   33
#define WSTR 6400

#define OFF_XS   0
#define OFF_YS   6656
#define OFF_HA   6720
#define OFF_HB   14400
#define OFF_WB   22080
#define OFF_AFA  34180
#define OFF_AFC  34308
#define OFF_WC   34436
#define SMEM_FLOATS 47236
#define SMEM_BYTES  (SMEM_FLOATS * 4)

__device__ __align__(16) float g_sum[63][4][128 * FS];
__device__ __align__(16) float g_ss2[63][4][128 * FS];
__device__ __align__(16) unsigned g_flags[NBLK * 32];   // 128B apart
__device__ unsigned g_release;

// hierarchical flag barrier: no serialized atomics
__device__ __forceinline__ void gridbar(unsigned gen) {
    __syncthreads();
    if (threadIdx.x == 0) {
        __threadfence();
        *(volatile unsigned*)&g_flags[blockIdx.x * 32] = gen;
    }
    if (blockIdx.x == 0) {
        if (threadIdx.x < NBLK) {
            volatile unsigned* fp = &g_flags[threadIdx.x * 32];
            while (*fp < gen) {}
        }
        __syncthreads();
        if (threadIdx.x == 0) {
            __threadfence();
            *(volatile unsigned*)&g_release = gen;
        }
        __syncthreads();
    } else {
        if (threadIdx.x == 0) {
            volatile unsigned* rp = &g_release;
            while (*rp < gen) {}
            __threadfence();
        }
        __syncthreads();
    }
}

__device__ __forceinline__ void cp_async16(float* dst_smem, const float* src) {
    unsigned d = (unsigned)__cvta_generic_to_shared(dst_smem);
    asm volatile("cp.async.cg.shared.global [%0], [%1], 16;\n" :: "r"(d), "l"(src));
}
__device__ __forceinline__ void cp_commit() { asm volatile("cp.async.commit_group;\n"); }
__device__ __forceinline__ void cp_wait0()  { asm volatile("cp.async.wait_group 0;\n" ::: "memory"); }

// float-only Cody-Waite sin: |x| < ~8, k small -> exact reduction
__device__ __forceinline__ float my_sin(float x) {
    float kf = rintf(x * 0.63661977236758134f);
    int k = (int)kf;
    float r = fmaf(-kf, 1.57079637050628662f, x);
    r = fmaf(-kf, -4.37113900018624283e-8f, r);
    float r2 = r * r;
    float sp = fmaf(r2, 2.7557314e-6f, -1.9841270e-4f);
    sp = fmaf(r2, sp, 8.3333331e-3f);
    sp = fmaf(r2, sp, -1.6666667e-1f);
    sp = r * fmaf(r2, sp, 1.0f);
    float cp = fmaf(r2, 2.4801587e-5f, -1.3888889e-3f);
    cp = fmaf(r2, cp, 4.1666666e-2f);
    cp = fmaf(r2, cp, -0.5f);
    cp = fmaf(r2, cp, 1.0f);
    int kk = k & 3;
    float res = (kk & 1) ? cp : sp;
    if (kk >= 2) res = -res;
    return res;
}

__device__ __forceinline__ void make_affine(const float* gs, const float* gq,
                                            const float* __restrict__ gamma,
                                            const float* __restrict__ beta,
                                            int nf, float* affA, float* affC) {
    int f = threadIdx.x;
    if (f < nf) {
        float mu  = __ldcg(&gs[f * FS]) * (1.f / 8192.f);
        float ex2 = __ldcg(&gq[f * FS]) * (1.f / 8192.f);
        float v = fmaxf(ex2 - mu * mu, 0.f) + 1e-6f;
        float rs = rsqrtf(v);
        rs = rs * (1.5f - 0.5f * v * rs * rs);
        float a = gamma[f] * rs;
        affA[f] = a;
        affC[f] = fmaf(-a, mu, beta[f]);
    }
}

// 512-thread stats (16 rows each) on pitch-HP buffer
__device__ __forceinline__ void accum_stats512(const float* buf, int nf,
                                               float* gs, float* gq) {
    int f = threadIdx.x & 127;
    int q = threadIdx.x >> 7;
    if (f < nf) {
        float s1 = 0.f, s2 = 0.f;
        const float* p = buf + q * 16 * HP + f;
#pragma unroll
        for (int r = 0; r < 16; r++) { float v = p[r * HP]; s1 += v; s2 = fmaf(v, v, s2); }
        atomicAdd(&gs[f * FS], s1);
        atomicAdd(&gq[f * FS], s2);
    }
}

// 256-thread stats (32 rows each) — runs in parallel with weight dump
__device__ __forceinline__ void accum_stats256(const float* buf, int nf,
                                               float* gs, float* gq) {
    int f = threadIdx.x & 127;
    int q = threadIdx.x >> 7;   // 0..1
    if (f < nf) {
        float s1 = 0.f, s2 = 0.f;
        const float* p = buf + q * 32 * HP + f;
#pragma unroll
        for (int r = 0; r < 32; r++) { float v = p[r * HP]; s1 += v; s2 = fmaf(v, v, s2); }
        atomicAdd(&gs[f * FS], s1);
        atomicAdd(&gq[f * FS], s2);
    }
}

// stats on xs(pitch XP, 100 cols) + ys (col 100), all 512 threads
__device__ __forceinline__ void accum_statsA(const float* xs, const float* ys,
                                             float* gs, float* gq) {
    int f = threadIdx.x & 127;
    int q = threadIdx.x >> 7;
    if (f < 101) {
        float s1 = 0.f, s2 = 0.f;
        if (f < 100) {
            const float* p = xs + q * 16 * XP + f;
#pragma unroll
            for (int r = 0; r < 16; r++) { float v = p[r * XP]; s1 += v; s2 = fmaf(v, v, s2); }
        } else {
            const float* p = ys + q * 16;
#pragma unroll
            for (int r = 0; r < 16; r++) { float v = p[r]; s1 += v; s2 = fmaf(v, v, s2); }
        }
        atomicAdd(&gs[f * FS], s1);
        atomicAdd(&gq[f * FS], s2);
    }
}

template<int K, int NC>
__device__ __forceinline__ void gemm64(const float* __restrict__ A,
                                       const float* __restrict__ wm,
                                       float* __restrict__ dst) {
    int rg = threadIdx.x >> 4, cg = threadIdx.x & 15;
    int r0 = rg * 4, j0 = cg * 7;
    float acc[4][7];
#pragma unroll
    for (int i = 0; i < 4; i++)
#pragma unroll
        for (int u = 0; u < 7; u++) acc[i][u] = 0.f;
    const float* a0 = A + r0 * HP;
    const float* wp = wm + j0;
#pragma unroll 4
    for (int k = 0; k < K; k++) {
        float x0 = a0[k], x1 = a0[HP + k], x2 = a0[2 * HP + k], x3 = a0[3 * HP + k];
        const float* wr = wp + k * NC;
#pragma unroll
        for (int u = 0; u < 7; u++) {
            float wv = wr[u];
            acc[0][u] = fmaf(x0, wv, acc[0][u]);
            acc[1][u] = fmaf(x1, wv, acc[1][u]);
            acc[2][u] = fmaf(x2, wv, acc[2][u]);
            acc[3][u] = fmaf(x3, wv, acc[3][u]);
        }
    }
#pragma unroll
    for (int u = 0; u < 7; u++) {
        int j = j0 + u;
        if (j < NC) {
#pragma unroll
            for (int i = 0; i < 4; i++) dst[(r0 + i) * HP + j] = acc[i][u];
        }
    }
}

// issued by threads 256..511 only (t = tid-256, 256 threads)
__device__ __forceinline__ void prefetch_W256(float* Wcbuf, const float* W, int row0, int t0) {
    int t = threadIdx.x - 256;
    for (int i = t; i < RPB * 25; i += 256) {
        int r = i / 25, c = i % 25;
        cp_async16(Wcbuf + r * 100 + c * 4,
                   W + ((size_t)(row0 + r) * 64 + t0) * 100 + c * 4);
    }
    cp_commit();
}

__global__ void __launch_bounds__(NTH, 1)
fullnn(const float* __restrict__ W,
       const float* __restrict__ y_init, const float* __restrict__ z_init,
       const float* __restrict__ g0, const float* __restrict__ b0,
       const float* __restrict__ g1, const float* __restrict__ b1,
       const float* __restrict__ g2, const float* __restrict__ b2,
       const float* __restrict__ g3, const float* __restrict__ b3,
       const float* __restrict__ w0, const float* __restrict__ w1,
       const float* __restrict__ w2,
       float* __restrict__ out)
{
    extern __shared__ float sm[];
    float* xs   = sm + OFF_XS;
    float* ys   = sm + OFF_YS;
    float* hA   = sm + OFF_HA;
    float* hB   = sm + OFF_HB;
    float* wb   = sm + OFF_WB;
    float* affA = sm + OFF_AFA;
    float* affC = sm + OFF_AFC;
    float* Wc   = sm + OFF_WC;

    const int tid  = threadIdx.x;
    const int bk   = blockIdx.x;
    const int row0 = bk * RPB;
    const int r_ = tid >> 3, q_ = tid & 7;

    unsigned gen = *(volatile unsigned*)&g_release;   // replay-safe baseline

    // prefetch W[0], W[1] (all threads)
    for (int i = tid; i < RPB * 25; i += NTH) {
        int r = i / 25, c = i % 25;
        cp_async16(Wc + r * 100 + c * 4, W + ((size_t)(row0 + r) * 64 + 0) * 100 + c * 4);
        cp_async16(Wc + WSTR + r * 100 + c * 4, W + ((size_t)(row0 + r) * 64 + 1) * 100 + c * 4);
    }
    cp_commit();

    {   // zero stats
        float4* p1 = (float4*)&g_sum[0][0][0];
        float4* p2 = (float4*)&g_ss2[0][0][0];
        int n4 = 63 * 4 * 128 * FS / 4;
        for (int i = bk * NTH + tid; i < n4; i += NBLK * NTH) {
            p1[i] = make_float4(0.f, 0.f, 0.f, 0.f);
            p2[i] = make_float4(0.f, 0.f, 0.f, 0.f);
        }
    }
    const float y0v = y_init[0];
    const float z0v = z_init[0];
    for (int i = tid; i < RPB * 100; i += NTH) {
        int r = i / 100, d = i % 100;
        xs[r * XP + d] = 1.57079632679489662f;
    }
    for (int r = tid; r < RPB; r += NTH) ys[r] = y0v;
    cp_wait0();
    gridbar(++gen);

    for (int s = 0; s < 63; s++) {
        // ---- Phase A: BN3 affine (prev), x/y update, stats0, stage w0
        cp_wait0();
        if (s > 0)
            make_affine(g_sum[s-1][3], g_ss2[s-1][3], g3 + (s-1)*100, b3 + (s-1)*100, 100, affA, affC);
        __syncthreads();
        {
            float ec = expf(-0.3f * (1.0f - (float)s * (1.0f / 64.0f)));
            float yold = ys[r_];
            const float* Wold = Wc + (s & 1) * WSTR + r_ * 100;
            const float* Wnew = Wc + ((s + 1) & 1) * WSTR + r_ * 100;
            float ssin = 0.f, zdot = 0.f;
            for (int d = q_; d < 100; d += 8) {
                float dw = Wnew[d] - Wold[d];
                float xn = fmaf(0.3f * dw, yold, xs[r_ * XP + d]);
                xs[r_ * XP + d] = xn;
                ssin += my_sin(xn);
                float zv = (s == 0) ? z0v : fmaf(affA[d], hB[r_ * HP + d], affC[d]) * 0.01f;
                zdot = fmaf(zv, dw, zdot);
            }
            ssin += __shfl_xor_sync(0xffffffffu, ssin, 1);
            ssin += __shfl_xor_sync(0xffffffffu, ssin, 2);
            ssin += __shfl_xor_sync(0xffffffffu, ssin, 4);
            zdot += __shfl_xor_sync(0xffffffffu, zdot, 1);
            zdot += __shfl_xor_sync(0xffffffffu, zdot, 2);
            zdot += __shfl_xor_sync(0xffffffffu, zdot, 4);
            if (q_ == 0) {
                float tc = 0.1f * ssin;
                float dr = fmaf(-0.1f, yold, 0.045f * ec * tc * tc * tc);
                ys[r_] = yold - dr * (1.0f / 64.0f) + zdot;
            }
        }
        __syncthreads();
        accum_statsA(xs, ys, g_sum[s][0], g_ss2[s][0]);
        {   // stage w0
            const float2* src = (const float2*)(w0 + (size_t)s * 11110);
            float2* dst = (float2*)wb;
            for (int i = tid; i < 5555; i += NTH) dst[i] = src[i];
        }
        gridbar(++gen);

        // ---- Phase B: BN0 apply (from xs/ys), GEMM0 || load w1, dump w1 || stats1
        make_affine(g_sum[s][0], g_ss2[s][0], g0 + s*101, b0 + s*101, 101, affA, affC);
        __syncthreads();
        for (int i = tid; i < RPB * 101; i += NTH) {
            int r = i / 101, f = i % 101;
            float v = (f < 100) ? xs[r * XP + f] : ys[r];
            hA[r * HP + f] = fmaf(affA[f], v, affC[f]);
        }
        __syncthreads();
        {
            float4 wreg[12];
            if (tid < 256) gemm64<101, 110>(hA, wb, hB);
            else {
                const float4* src = (const float4*)(w1 + (size_t)s * 12100);
                int t = tid - 256;
#pragma unroll
                for (int i = 0; i < 12; i++) {
                    int idx = t + i * 256;
                    wreg[i] = (idx < 3025) ? src[idx] : make_float4(0.f, 0.f, 0.f, 0.f);
                }
            }
            __syncthreads();
            if (tid >= 256) {
                float4* dst = (float4*)wb;
                int t = tid - 256;
#pragma unroll
                for (int i = 0; i < 12; i++) {
                    int idx = t + i * 256;
                    if (idx < 3025) dst[idx] = wreg[i];
                }
            } else accum_stats256(hB, 110, g_sum[s][1], g_ss2[s][1]);
        }
        gridbar(++gen);

        // ---- Phase C: BN1+relu, GEMM1 || load w2, dump w2 || stats2
        make_affine(g_sum[s][1], g_ss2[s][1], g1 + s*110, b1 + s*110, 110, affA, affC);
        __syncthreads();
        for (int i = tid; i < RPB * 110; i += NTH) {
            int r = i / 110, f = i % 110;
            hA[r * HP + f] = fmaxf(fmaf(affA[f], hB[r * HP + f], affC[f]), 0.f);
        }
        __syncthreads();
        {
            float4 wreg[11];
            if (tid < 256) gemm64<110, 110>(hA, wb, hB);
            else {
                const float4* src = (const float4*)(w2 + (size_t)s * 11000);
                int t = tid - 256;
#pragma unroll
                for (int i = 0; i < 11; i++) {
                    int idx = t + i * 256;
                    wreg[i] = (idx < 2750) ? src[idx] : make_float4(0.f, 0.f, 0.f, 0.f);
                }
            }
            __syncthreads();
            if (tid >= 256) {
                float4* dst = (float4*)wb;
                int t = tid - 256;
#pragma unroll
                for (int i = 0; i < 11; i++) {
                    int idx = t + i * 256;
                    if (idx < 2750) dst[idx] = wreg[i];
                }
            } else accum_stats256(hB, 110, g_sum[s][2], g_ss2[s][2]);
        }
        gridbar(++gen);

        // ---- Phase D: BN2+relu, GEMM2 || prefetch W[s+2], stats3
        make_affine(g_sum[s][2], g_ss2[s][2], g2 + s*110, b2 + s*110, 110, affA, affC);
        __syncthreads();
        for (int i = tid; i < RPB * 110; i += NTH) {
            int r = i / 110, f = i % 110;
            hA[r * HP + f] = fmaxf(fmaf(affA[f], hB[r * HP + f], affC[f]), 0.f);
        }
        __syncthreads();
        if (tid < 256) gemm64<110, 100>(hA, wb, hB);
        else if (s <= 61) prefetch_W256(Wc + (s & 1) * WSTR, W, row0, s + 2);
        __syncthreads();
        accum_stats512(hB, 100, g_sum[s][3], g_ss2[s][3]);
        gridbar(++gen);
    }

    // ---- Final extra step; write outputs
    make_affine(g_sum[62][3], g_ss2[62][3], g3 + 62*100, b3 + 62*100, 100, affA, affC);
    __syncthreads();
    {
        float ec = expf(-0.3f * (1.0f - 62.0f / 64.0f));
        float yold = ys[r_];
        const float* Wold = Wc + r_ * 100;           // W[62]
        const float* Wnew = Wc + WSTR + r_ * 100;    // W[63]
        float ssin = 0.f, zdot = 0.f;
        for (int d = q_; d < 100; d += 8) {
            float dw = Wnew[d] - Wold[d];
            float xn = fmaf(0.3f * dw, yold, xs[r_ * XP + d]);
            out[(size_t)(row0 + r_) * 100 + d] = xn;
            ssin += my_sin(xn);
            float zv = fmaf(affA[d], hB[r_ * HP + d], affC[d]) * 0.01f;
            zdot = fmaf(zv, dw, zdot);
        }
        ssin += __shfl_xor_sync(0xffffffffu, ssin, 1);
        ssin += __shfl_xor_sync(0xffffffffu, ssin, 2);
        ssin += __shfl_xor_sync(0xffffffffu, ssin, 4);
        zdot += __shfl_xor_sync(0xffffffffu, zdot, 1);
        zdot += __shfl_xor_sync(0xffffffffu, zdot, 2);
        zdot += __shfl_xor_sync(0xffffffffu, zdot, 4);
        if (q_ == 0) {
            float tc = 0.1f * ssin;
            float dr = fmaf(-0.1f, yold, 0.045f * ec * tc * tc * tc);
            out[(size_t)8192 * 100 + row0 + r_] = yold - dr * (1.0f / 64.0f) + zdot;
        }
    }
}

extern "C" void kernel_launch(void* const* d_in, const int* in_sizes, int n_in,
                              void* d_out, int out_size) {
    cudaFuncSetAttribute(fullnn, cudaFuncAttributeMaxDynamicSharedMemorySize, SMEM_BYTES);
    fullnn<<<NBLK, NTH, SMEM_BYTES>>>(
        (const float*)d_in[0], (const float*)d_in[1], (const float*)d_in[2],
        (const float*)d_in[3], (const float*)d_in[4], (const float*)d_in[5],
        (const float*)d_in[6], (const float*)d_in[7], (const float*)d_in[8],
        (const float*)d_in[9], (const float*)d_in[10], (const float*)d_in[11],
        (const float*)d_in[12], (const float*)d_in[13],
        (float*)d_out);
}

// round 6
// speedup vs baseline: 1.2994x; 1.0616x over previous
#include <cuda_runtime.h>
#include <math.h>

#define NBLK 128
#define NTH  512
#define RPB  64
#define XP   104
#define HP   120
#define FS   40          // 8 shards per feature, 16B aligned
#define WSTR 6400

#define OFF_XS   0
#define OFF_YS   6656
#define OFF_HA   6720
#define OFF_HB   14400
#define OFF_WB   22080
#define OFF_AFA  34184
#define OFF_AFC  34312
#define OFF_WC   34440
#define SMEM_FLOATS 47240
#define SMEM_BYTES  (SMEM_FLOATS * 4)

__device__ __align__(16) float g_sum[63][4][128 * FS];
__device__ __align__(16) float g_ss2[63][4][128 * FS];
__device__ __align__(16) unsigned g_flags[NBLK * 32];
__device__ unsigned g_release;

__device__ __forceinline__ void gridbar(unsigned gen) {
    __syncthreads();
    if (threadIdx.x == 0) {
        __threadfence();
        *(volatile unsigned*)&g_flags[blockIdx.x * 32] = gen;
    }
    if (blockIdx.x == 0) {
        if (threadIdx.x < NBLK) {
            volatile unsigned* fp = &g_flags[threadIdx.x * 32];
            while (*fp < gen) {}
        }
        __syncthreads();
        if (threadIdx.x == 0) {
            __threadfence();
            *(volatile unsigned*)&g_release = gen;
        }
        __syncthreads();
    } else {
        if (threadIdx.x == 0) {
            volatile unsigned* rp = &g_release;
            while (*rp < gen) {}
            __threadfence();
        }
        __syncthreads();
    }
}

__device__ __forceinline__ void cp_async16(float* dst_smem, const float* src) {
    unsigned d = (unsigned)__cvta_generic_to_shared(dst_smem);
    asm volatile("cp.async.cg.shared.global [%0], [%1], 16;\n" :: "r"(d), "l"(src));
}
__device__ __forceinline__ void cp_commit() { asm volatile("cp.async.commit_group;\n"); }
__device__ __forceinline__ void cp_wait0()  { asm volatile("cp.async.wait_group 0;\n" ::: "memory"); }

#define PACK_DUP(dst, x) asm("mov.b64 %0, {%1, %1};" : "=l"(dst) : "f"(x))
#define FMA2(acc, a, b)  asm("fma.rn.f32x2 %0, %1, %2, %0;" : "+l"(acc) : "l"(a), "l"(b))

// float-only Cody-Waite sin (|x| small here)
__device__ __forceinline__ float my_sin(float x) {
    float kf = rintf(x * 0.63661977236758134f);
    int k = (int)kf;
    float r = fmaf(-kf, 1.57079637050628662f, x);
    r = fmaf(-kf, -4.37113900018624283e-8f, r);
    float r2 = r * r;
    float sp = fmaf(r2, 2.7557314e-6f, -1.9841270e-4f);
    sp = fmaf(r2, sp, 8.3333331e-3f);
    sp = fmaf(r2, sp, -1.6666667e-1f);
    sp = r * fmaf(r2, sp, 1.0f);
    float cp = fmaf(r2, 2.4801587e-5f, -1.3888889e-3f);
    cp = fmaf(r2, cp, 4.1666666e-2f);
    cp = fmaf(r2, cp, -0.5f);
    cp = fmaf(r2, cp, 1.0f);
    int kk = k & 3;
    float res = (kk & 1) ? cp : sp;
    if (kk >= 2) res = -res;
    return res;
}

__device__ __forceinline__ void make_affine(const float* gs, const float* gq,
                                            const float* __restrict__ gamma,
                                            const float* __restrict__ beta,
                                            int nf, float* affA, float* affC) {
    int f = threadIdx.x;
    if (f < nf) {
        float4 a0 = __ldcg((const float4*)&gs[f * FS]);
        float4 a1 = __ldcg((const float4*)&gs[f * FS + 4]);
        float4 b0 = __ldcg((const float4*)&gq[f * FS]);
        float4 b1 = __ldcg((const float4*)&gq[f * FS + 4]);
        float mu  = (((a0.x + a0.y) + (a0.z + a0.w)) + ((a1.x + a1.y) + (a1.z + a1.w))) * (1.f / 8192.f);
        float ex2 = (((b0.x + b0.y) + (b0.z + b0.w)) + ((b1.x + b1.y) + (b1.z + b1.w))) * (1.f / 8192.f);
        float v = fmaxf(ex2 - mu * mu, 0.f) + 1e-6f;
        float rs = rsqrtf(v);
        rs = rs * (1.5f - 0.5f * v * rs * rs);
        float a = gamma[f] * rs;
        affA[f] = a;
        affC[f] = fmaf(-a, mu, beta[f]);
    }
}

// tid<128 only: one thread per feature, 64 rows, 1 atomic per feature to shard
__device__ __forceinline__ void stats128(const float* buf, int pitch, int nf,
                                         float* gs, float* gq) {
    int f = threadIdx.x;
    if (f < nf) {
        float s1 = 0.f, s2 = 0.f;
        const float* p = buf + f;
#pragma unroll 8
        for (int r = 0; r < RPB; r++) { float v = p[r * pitch]; s1 += v; s2 = fmaf(v, v, s2); }
        int sh = blockIdx.x & 7;
        atomicAdd(&gs[f * FS + sh], s1);
        atomicAdd(&gq[f * FS + sh], s2);
    }
}

// tid<128: stats over xs (100 cols, pitch XP) + ys (feature 100)
__device__ __forceinline__ void stats128A(const float* xs, const float* ys,
                                          float* gs, float* gq) {
    int f = threadIdx.x;
    if (f < 101) {
        float s1 = 0.f, s2 = 0.f;
        if (f < 100) {
            const float* p = xs + f;
#pragma unroll 8
            for (int r = 0; r < RPB; r++) { float v = p[r * XP]; s1 += v; s2 = fmaf(v, v, s2); }
        } else {
#pragma unroll 8
            for (int r = 0; r < RPB; r++) { float v = ys[r]; s1 += v; s2 = fmaf(v, v, s2); }
        }
        int sh = blockIdx.x & 7;
        atomicAdd(&gs[f * FS + sh], s1);
        atomicAdd(&gq[f * FS + sh], s2);
    }
}

// FFMA2 GEMM: 64 x NC = 64 x K @ K x NC. tid<256. Thread: 4 rows x 4 col-pairs
// (cols j = cg*2 + v*32). W row pitch NC (even), loads are lane-consecutive f32x2.
template<int K, int NC>
__device__ __forceinline__ void gemm64(const float* __restrict__ A,
                                       const float* __restrict__ wm,
                                       float* __restrict__ dst) {
    int rg = threadIdx.x >> 4, cg = threadIdx.x & 15;
    int r0 = rg * 4;
    unsigned long long acc[4][4] = {};
    const float* a0 = A + r0 * HP;
#pragma unroll 2
    for (int k = 0; k < K; k++) {
        unsigned long long X0, X1, X2, X3;
        PACK_DUP(X0, a0[k]);
        PACK_DUP(X1, a0[HP + k]);
        PACK_DUP(X2, a0[2 * HP + k]);
        PACK_DUP(X3, a0[3 * HP + k]);
        const unsigned long long* wr = (const unsigned long long*)(wm + k * NC + cg * 2);
#pragma unroll
        for (int v = 0; v < 4; v++) {
            unsigned long long wv = wr[v * 16];
            FMA2(acc[0][v], X0, wv);
            FMA2(acc[1][v], X1, wv);
            FMA2(acc[2][v], X2, wv);
            FMA2(acc[3][v], X3, wv);
        }
    }
#pragma unroll
    for (int v = 0; v < 4; v++) {
        int j = cg * 2 + v * 32;
        if (j + 1 < NC) {
#pragma unroll
            for (int i = 0; i < 4; i++)
                *(float2*)&dst[(r0 + i) * HP + j] = *(float2*)&acc[i][v];
        }
    }
}

__device__ __forceinline__ void prefetch_W256(float* Wcbuf, const float* W, int row0, int t0) {
    int t = threadIdx.x - 256;
    for (int i = t; i < RPB * 25; i += 256) {
        int r = i / 25, c = i % 25;
        cp_async16(Wcbuf + r * 100 + c * 4,
                   W + ((size_t)(row0 + r) * 64 + t0) * 100 + c * 4);
    }
    cp_commit();
}

__global__ void __launch_bounds__(NTH, 1)
fullnn(const float* __restrict__ W,
       const float* __restrict__ y_init, const float* __restrict__ z_init,
       const float* __restrict__ g0, const float* __restrict__ b0,
       const float* __restrict__ g1, const float* __restrict__ b1,
       const float* __restrict__ g2, const float* __restrict__ b2,
       const float* __restrict__ g3, const float* __restrict__ b3,
       const float* __restrict__ w0, const float* __restrict__ w1,
       const float* __restrict__ w2,
       float* __restrict__ out)
{
    extern __shared__ float sm[];
    float* xs   = sm + OFF_XS;
    float* ys   = sm + OFF_YS;
    float* hA   = sm + OFF_HA;
    float* hB   = sm + OFF_HB;
    float* wb   = sm + OFF_WB;
    float* affA = sm + OFF_AFA;
    float* affC = sm + OFF_AFC;
    float* Wc   = sm + OFF_WC;

    const int tid  = threadIdx.x;
    const int bk   = blockIdx.x;
    const int row0 = bk * RPB;
    const int r_ = tid >> 3, q_ = tid & 7;

    unsigned gen = *(volatile unsigned*)&g_release;

    for (int i = tid; i < RPB * 25; i += NTH) {
        int r = i / 25, c = i % 25;
        cp_async16(Wc + r * 100 + c * 4, W + ((size_t)(row0 + r) * 64 + 0) * 100 + c * 4);
        cp_async16(Wc + WSTR + r * 100 + c * 4, W + ((size_t)(row0 + r) * 64 + 1) * 100 + c * 4);
    }
    cp_commit();

    {   // zero stats
        float4* p1 = (float4*)&g_sum[0][0][0];
        float4* p2 = (float4*)&g_ss2[0][0][0];
        int n4 = 63 * 4 * 128 * FS / 4;
        for (int i = bk * NTH + tid; i < n4; i += NBLK * NTH) {
            p1[i] = make_float4(0.f, 0.f, 0.f, 0.f);
            p2[i] = make_float4(0.f, 0.f, 0.f, 0.f);
        }
    }
    const float y0v = y_init[0];
    const float z0v = z_init[0];
    for (int i = tid; i < RPB * 100; i += NTH) {
        int r = i / 100, d = i % 100;
        xs[r * XP + d] = 1.57079632679489662f;
    }
    for (int r = tid; r < RPB; r += NTH) ys[r] = y0v;
    cp_wait0();
    gridbar(++gen);

    for (int s = 0; s < 63; s++) {
        // ---- Phase A: BN3 affine (prev), x/y update, stats0 || stage w0
        cp_wait0();
        if (s > 0)
            make_affine(g_sum[s-1][3], g_ss2[s-1][3], g3 + (s-1)*100, b3 + (s-1)*100, 100, affA, affC);
        __syncthreads();
        {
            float ec = expf(-0.3f * (1.0f - (float)s * (1.0f / 64.0f)));
            float yold = ys[r_];
            const float* Wold = Wc + (s & 1) * WSTR + r_ * 100;
            const float* Wnew = Wc + ((s + 1) & 1) * WSTR + r_ * 100;
            float ssin = 0.f, zdot = 0.f;
            for (int d = q_; d < 100; d += 8) {
                float dw = Wnew[d] - Wold[d];
                float xn = fmaf(0.3f * dw, yold, xs[r_ * XP + d]);
                xs[r_ * XP + d] = xn;
                ssin += my_sin(xn);
                float zv = (s == 0) ? z0v : fmaf(affA[d], hB[r_ * HP + d], affC[d]) * 0.01f;
                zdot = fmaf(zv, dw, zdot);
            }
            ssin += __shfl_xor_sync(0xffffffffu, ssin, 1);
            ssin += __shfl_xor_sync(0xffffffffu, ssin, 2);
            ssin += __shfl_xor_sync(0xffffffffu, ssin, 4);
            zdot += __shfl_xor_sync(0xffffffffu, zdot, 1);
            zdot += __shfl_xor_sync(0xffffffffu, zdot, 2);
            zdot += __shfl_xor_sync(0xffffffffu, zdot, 4);
            if (q_ == 0) {
                float tc = 0.1f * ssin;
                float dr = fmaf(-0.1f, yold, 0.045f * ec * tc * tc * tc);
                ys[r_] = yold - dr * (1.0f / 64.0f) + zdot;
            }
        }
        __syncthreads();
        if (tid < 128) stats128A(xs, ys, g_sum[s][0], g_ss2[s][0]);
        else {
            const float2* src = (const float2*)(w0 + (size_t)s * 11110);
            float2* dst = (float2*)wb;
            for (int i = tid - 128; i < 5555; i += 384) dst[i] = src[i];
        }
        gridbar(++gen);

        // ---- Phase B: BN0 apply, GEMM0 || load w1, dump w1 || stats1
        make_affine(g_sum[s][0], g_ss2[s][0], g0 + s*101, b0 + s*101, 101, affA, affC);
        __syncthreads();
        for (int i = tid; i < RPB * 101; i += NTH) {
            int r = i / 101, f = i % 101;
            float v = (f < 100) ? xs[r * XP + f] : ys[r];
            hA[r * HP + f] = fmaf(affA[f], v, affC[f]);
        }
        __syncthreads();
        {
            float4 wreg[12];
            if (tid < 256) gemm64<101, 110>(hA, wb, hB);
            else {
                const float4* src = (const float4*)(w1 + (size_t)s * 12100);
                int t = tid - 256;
#pragma unroll
                for (int i = 0; i < 12; i++) {
                    int idx = t + i * 256;
                    wreg[i] = (idx < 3025) ? src[idx] : make_float4(0.f, 0.f, 0.f, 0.f);
                }
            }
            __syncthreads();
            if (tid >= 256) {
                float4* dst = (float4*)wb;
                int t = tid - 256;
#pragma unroll
                for (int i = 0; i < 12; i++) {
                    int idx = t + i * 256;
                    if (idx < 3025) dst[idx] = wreg[i];
                }
            } else if (tid < 128) stats128(hB, HP, 110, g_sum[s][1], g_ss2[s][1]);
        }
        gridbar(++gen);

        // ---- Phase C: BN1+relu, GEMM1 || load w2, dump w2 || stats2
        make_affine(g_sum[s][1], g_ss2[s][1], g1 + s*110, b1 + s*110, 110, affA, affC);
        __syncthreads();
        for (int i = tid; i < RPB * 110; i += NTH) {
            int r = i / 110, f = i % 110;
            hA[r * HP + f] = fmaxf(fmaf(affA[f], hB[r * HP + f], affC[f]), 0.f);
        }
        __syncthreads();
        {
            float4 wreg[11];
            if (tid < 256) gemm64<110, 110>(hA, wb, hB);
            else {
                const float4* src = (const float4*)(w2 + (size_t)s * 11000);
                int t = tid - 256;
#pragma unroll
                for (int i = 0; i < 11; i++) {
                    int idx = t + i * 256;
                    wreg[i] = (idx < 2750) ? src[idx] : make_float4(0.f, 0.f, 0.f, 0.f);
                }
            }
            __syncthreads();
            if (tid >= 256) {
                float4* dst = (float4*)wb;
                int t = tid - 256;
#pragma unroll
                for (int i = 0; i < 11; i++) {
                    int idx = t + i * 256;
                    if (idx < 2750) dst[idx] = wreg[i];
                }
            } else if (tid < 128) stats128(hB, HP, 110, g_sum[s][2], g_ss2[s][2]);
        }
        gridbar(++gen);

        // ---- Phase D: BN2+relu, GEMM2 || prefetch W[s+2], stats3
        make_affine(g_sum[s][2], g_ss2[s][2], g2 + s*110, b2 + s*110, 110, affA, affC);
        __syncthreads();
        for (int i = tid; i < RPB * 110; i += NTH) {
            int r = i / 110, f = i % 110;
            hA[r * HP + f] = fmaxf(fmaf(affA[f], hB[r * HP + f], affC[f]), 0.f);
        }
        __syncthreads();
        if (tid < 256) gemm64<110, 100>(hA, wb, hB);
        else if (s <= 61) prefetch_W256(Wc + (s & 1) * WSTR, W, row0, s + 2);
        __syncthreads();
        if (tid < 128) stats128(hB, HP, 100, g_sum[s][3], g_ss2[s][3]);
        gridbar(++gen);
    }

    // ---- Final extra step; write outputs
    make_affine(g_sum[62][3], g_ss2[62][3], g3 + 62*100, b3 + 62*100, 100, affA, affC);
    __syncthreads();
    {
        float ec = expf(-0.3f * (1.0f - 62.0f / 64.0f));
        float yold = ys[r_];
        const float* Wold = Wc + r_ * 100;
        const float* Wnew = Wc + WSTR + r_ * 100;
        float ssin = 0.f, zdot = 0.f;
        for (int d = q_; d < 100; d += 8) {
            float dw = Wnew[d] - Wold[d];
            float xn = fmaf(0.3f * dw, yold, xs[r_ * XP + d]);
            out[(size_t)(row0 + r_) * 100 + d] = xn;
            ssin += my_sin(xn);
            float zv = fmaf(affA[d], hB[r_ * HP + d], affC[d]) * 0.01f;
            zdot = fmaf(zv, dw, zdot);
        }
        ssin += __shfl_xor_sync(0xffffffffu, ssin, 1);
        ssin += __shfl_xor_sync(0xffffffffu, ssin, 2);
        ssin += __shfl_xor_sync(0xffffffffu, ssin, 4);
        zdot += __shfl_xor_sync(0xffffffffu, zdot, 1);
        zdot += __shfl_xor_sync(0xffffffffu, zdot, 2);
        zdot += __shfl_xor_sync(0xffffffffu, zdot, 4);
        if (q_ == 0) {
            float tc = 0.1f * ssin;
            float dr = fmaf(-0.1f, yold, 0.045f * ec * tc * tc * tc);
            out[(size_t)8192 * 100 + row0 + r_] = yold - dr * (1.0f / 64.0f) + zdot;
        }
    }
}

extern "C" void kernel_launch(void* const* d_in, const int* in_sizes, int n_in,
                              void* d_out, int out_size) {
    cudaFuncSetAttribute(fullnn, cudaFuncAttributeMaxDynamicSharedMemorySize, SMEM_BYTES);
    fullnn<<<NBLK, NTH, SMEM_BYTES>>>(
        (const float*)d_in[0], (const float*)d_in[1], (const float*)d_in[2],
        (const float*)d_in[3], (const float*)d_in[4], (const float*)d_in[5],
        (const float*)d_in[6], (const float*)d_in[7], (const float*)d_in[8],
        (const float*)d_in[9], (const float*)d_in[10], (const float*)d_in[11],
        (const float*)d_in[12], (const float*)d_in[13],
        (float*)d_out);
}

// round 7
// speedup vs baseline: 1.3240x; 1.0190x over previous
#include <cuda_runtime.h>
#include <math.h>

#define NBLK 128
#define NTH  512
#define RPB  64
#define XP   104
#define HP   120          // hB pitch
#define HP2  224          // hA2 (duplicated-pair) pitch in floats
#define FS   40
#define WSTR 6400

#define OFF_XS   0
#define OFF_YS   6656
#define OFF_HA2  6720
#define OFF_HB   21056
#define OFF_WB   28736
#define OFF_AFA  40836
#define OFF_AFC  40964
#define OFF_WC   41092
#define SMEM_FLOATS 53892
#define SMEM_BYTES  (SMEM_FLOATS * 4)

__device__ __align__(16) float g_sum[63][4][128 * FS];
__device__ __align__(16) float g_ss2[63][4][128 * FS];
__device__ __align__(16) unsigned g_flags[NBLK * 32];
__device__ unsigned g_release;
__device__ __align__(16) unsigned g_arrive[256];

// one-time init barrier (flag-based, replay-safe monotonic gen)
__device__ __forceinline__ void gridbar(unsigned gen) {
    __syncthreads();
    if (threadIdx.x == 0) {
        __threadfence();
        *(volatile unsigned*)&g_flags[blockIdx.x * 32] = gen;
    }
    if (blockIdx.x == 0) {
        if (threadIdx.x < NBLK) {
            volatile unsigned* fp = &g_flags[threadIdx.x * 32];
            while (*fp < gen) {}
        }
        __syncthreads();
        if (threadIdx.x == 0) { __threadfence(); *(volatile unsigned*)&g_release = gen; }
        __syncthreads();
    } else {
        if (threadIdx.x == 0) {
            volatile unsigned* rp = &g_release;
            while (*rp < gen) {}
            __threadfence();
        }
        __syncthreads();
    }
}

// async dataflow sync: block announces its stats are pushed / waits for all
__device__ __forceinline__ void arrive_cnt(int idx) {   // tid0, after __syncthreads
    __threadfence();
    atomicAdd(&g_arrive[idx], 1u);
}
__device__ __forceinline__ void wait_cnt(int idx) {     // tid0; caller syncs after
    volatile unsigned* p = &g_arrive[idx];
    while (*p < NBLK) {}
    __threadfence();
}

__device__ __forceinline__ void cp_async16(float* dst_smem, const float* src) {
    unsigned d = (unsigned)__cvta_generic_to_shared(dst_smem);
    asm volatile("cp.async.cg.shared.global [%0], [%1], 16;\n" :: "r"(d), "l"(src));
}
__device__ __forceinline__ void cp_commit() { asm volatile("cp.async.commit_group;\n"); }
__device__ __forceinline__ void cp_wait0()  { asm volatile("cp.async.wait_group 0;\n" ::: "memory"); }

#define FMA2(acc, a, b) asm("fma.rn.f32x2 %0, %1, %2, %0;" : "+l"(acc) : "l"(a), "l"(b))

__device__ __forceinline__ float my_sin(float x) {
    float kf = rintf(x * 0.63661977236758134f);
    int k = (int)kf;
    float r = fmaf(-kf, 1.57079637050628662f, x);
    r = fmaf(-kf, -4.37113900018624283e-8f, r);
    float r2 = r * r;
    float sp = fmaf(r2, 2.7557314e-6f, -1.9841270e-4f);
    sp = fmaf(r2, sp, 8.3333331e-3f);
    sp = fmaf(r2, sp, -1.6666667e-1f);
    sp = r * fmaf(r2, sp, 1.0f);
    float cp = fmaf(r2, 2.4801587e-5f, -1.3888889e-3f);
    cp = fmaf(r2, cp, 4.1666666e-2f);
    cp = fmaf(r2, cp, -0.5f);
    cp = fmaf(r2, cp, 1.0f);
    int kk = k & 3;
    float res = (kk & 1) ? cp : sp;
    if (kk >= 2) res = -res;
    return res;
}

__device__ __forceinline__ void make_affine(const float* gs, const float* gq,
                                            const float* __restrict__ gamma,
                                            const float* __restrict__ beta,
                                            int nf, float* affA, float* affC) {
    int f = threadIdx.x;
    if (f < nf) {
        float4 a0 = __ldcg((const float4*)&gs[f * FS]);
        float4 a1 = __ldcg((const float4*)&gs[f * FS + 4]);
        float4 b0 = __ldcg((const float4*)&gq[f * FS]);
        float4 b1 = __ldcg((const float4*)&gq[f * FS + 4]);
        float mu  = (((a0.x + a0.y) + (a0.z + a0.w)) + ((a1.x + a1.y) + (a1.z + a1.w))) * (1.f / 8192.f);
        float ex2 = (((b0.x + b0.y) + (b0.z + b0.w)) + ((b1.x + b1.y) + (b1.z + b1.w))) * (1.f / 8192.f);
        float v = fmaxf(ex2 - mu * mu, 0.f) + 1e-6f;
        float rs = rsqrtf(v);
        rs = rs * (1.5f - 0.5f * v * rs * rs);
        float a = gamma[f] * rs;
        affA[f] = a;
        affC[f] = fmaf(-a, mu, beta[f]);
    }
}

// one thread per feature, 64 rows, 1 atomic pair per feature to this block's shard
__device__ __forceinline__ void stats128(const float* buf, int pitch, int nf,
                                         float* gs, float* gq) {
    int f = threadIdx.x;
    if (f < nf) {
        float s1 = 0.f, s2 = 0.f;
        const float* p = buf + f;
#pragma unroll 8
        for (int r = 0; r < RPB; r++) { float v = p[r * pitch]; s1 += v; s2 = fmaf(v, v, s2); }
        int sh = blockIdx.x & 7;
        atomicAdd(&gs[f * FS + sh], s1);
        atomicAdd(&gq[f * FS + sh], s2);
    }
}

// FFMA2 GEMM, A stored as duplicated pairs (pitch HP2). tid<256.
template<int K, int NC>
__device__ __forceinline__ void gemm64(const float* __restrict__ A,
                                       const float* __restrict__ wm,
                                       float* __restrict__ dst) {
    int rg = threadIdx.x >> 4, cg = threadIdx.x & 15;
    int r0 = rg * 4;
    unsigned long long acc[4][4] = {};
    const unsigned long long* a0 = (const unsigned long long*)(A + r0 * HP2);
    const unsigned long long* a1 = (const unsigned long long*)(A + (r0 + 1) * HP2);
    const unsigned long long* a2 = (const unsigned long long*)(A + (r0 + 2) * HP2);
    const unsigned long long* a3 = (const unsigned long long*)(A + (r0 + 3) * HP2);
#pragma unroll 2
    for (int k = 0; k < K; k++) {
        unsigned long long X0 = a0[k], X1 = a1[k], X2 = a2[k], X3 = a3[k];
        const unsigned long long* wr = (const unsigned long long*)(wm + k * NC) + cg;
#pragma unroll
        for (int v = 0; v < 4; v++) {
            unsigned long long wv = wr[v * 16];
            FMA2(acc[0][v], X0, wv);
            FMA2(acc[1][v], X1, wv);
            FMA2(acc[2][v], X2, wv);
            FMA2(acc[3][v], X3, wv);
        }
    }
#pragma unroll
    for (int v = 0; v < 4; v++) {
        int j = cg * 2 + v * 32;
        if (j + 1 < NC) {
#pragma unroll
            for (int i = 0; i < 4; i++)
                *(float2*)&dst[(r0 + i) * HP + j] = *(float2*)&acc[i][v];
        }
    }
}

__device__ __forceinline__ void prefetch_W256(float* Wcbuf, const float* W, int row0, int t0) {
    int t = threadIdx.x - 256;
    for (int i = t; i < RPB * 25; i += 256) {
        int r = i / 25, c = i % 25;
        cp_async16(Wcbuf + r * 100 + c * 4,
                   W + ((size_t)(row0 + r) * 64 + t0) * 100 + c * 4);
    }
    cp_commit();
}

__global__ void __launch_bounds__(NTH, 1)
fullnn(const float* __restrict__ W,
       const float* __restrict__ y_init, const float* __restrict__ z_init,
       const float* __restrict__ g0, const float* __restrict__ b0,
       const float* __restrict__ g1, const float* __restrict__ b1,
       const float* __restrict__ g2, const float* __restrict__ b2,
       const float* __restrict__ g3, const float* __restrict__ b3,
       const float* __restrict__ w0, const float* __restrict__ w1,
       const float* __restrict__ w2,
       float* __restrict__ out)
{
    extern __shared__ float sm[];
    float* xs   = sm + OFF_XS;
    float* ys   = sm + OFF_YS;
    float* hA2  = sm + OFF_HA2;
    float* hB   = sm + OFF_HB;
    float* wb   = sm + OFF_WB;
    float* affA = sm + OFF_AFA;
    float* affC = sm + OFF_AFC;
    float* Wc   = sm + OFF_WC;

    const int tid  = threadIdx.x;
    const int bk   = blockIdx.x;
    const int row0 = bk * RPB;
    const int r_ = tid >> 3, q_ = tid & 7;

    unsigned gen = *(volatile unsigned*)&g_release;

    for (int i = tid; i < RPB * 25; i += NTH) {
        int r = i / 25, c = i % 25;
        cp_async16(Wc + r * 100 + c * 4, W + ((size_t)(row0 + r) * 64 + 0) * 100 + c * 4);
        cp_async16(Wc + WSTR + r * 100 + c * 4, W + ((size_t)(row0 + r) * 64 + 1) * 100 + c * 4);
    }
    cp_commit();

    {   // zero stats + arrival counters (disjoint slices)
        float4* p1 = (float4*)&g_sum[0][0][0];
        float4* p2 = (float4*)&g_ss2[0][0][0];
        int n4 = 63 * 4 * 128 * FS / 4;
        for (int i = bk * NTH + tid; i < n4; i += NBLK * NTH) {
            p1[i] = make_float4(0.f, 0.f, 0.f, 0.f);
            p2[i] = make_float4(0.f, 0.f, 0.f, 0.f);
        }
        if (bk == 0 && tid < 256) g_arrive[tid] = 0u;
    }
    const float y0v = y_init[0];
    const float z0v = z_init[0];
    for (int i = tid; i < RPB * 100; i += NTH) {
        int r = i / 100, d = i % 100;
        xs[r * XP + d] = 1.57079632679489662f;
    }
    for (int r = tid; r < RPB; r += NTH) ys[r] = y0v;
    cp_wait0();
    gridbar(++gen);   // single true barrier: zeroing visible everywhere

    for (int s = 0; s < 63; s++) {
        const int base = s * 4;
        // ---- Phase A: x update + sin (independent of stats3!), x-stats push,
        //      stage w0; then wait stats3, BN3 affine, y update, y-stat, arrive0
        cp_wait0();
        __syncthreads();
        float ssin = 0.f;
        {
            const float yold = ys[r_];
            const float* Wold = Wc + (s & 1) * WSTR + r_ * 100;
            const float* Wnew = Wc + ((s + 1) & 1) * WSTR + r_ * 100;
            for (int d = q_; d < 100; d += 8) {
                float dw = Wnew[d] - Wold[d];
                float xn = fmaf(0.3f * dw, yold, xs[r_ * XP + d]);
                xs[r_ * XP + d] = xn;
                ssin += my_sin(xn);
            }
        }
        __syncthreads();
        if (tid < 100) {            // x-feature stats -> stats0 shards (early!)
            float s1 = 0.f, s2 = 0.f;
            const float* p = xs + tid;
#pragma unroll 8
            for (int r = 0; r < RPB; r++) { float v = p[r * XP]; s1 += v; s2 = fmaf(v, v, s2); }
            int sh = bk & 7;
            atomicAdd(&g_sum[s][0][tid * FS + sh], s1);
            atomicAdd(&g_ss2[s][0][tid * FS + sh], s2);
        } else if (tid >= 128) {    // stage w0
            const float2* src = (const float2*)(w0 + (size_t)s * 11110);
            float2* dst = (float2*)wb;
            for (int i = tid - 128; i < 5555; i += 384) dst[i] = src[i];
        }
        if (s > 0) {
            if (tid == 0) wait_cnt(base - 1);        // stats3 of s-1
            __syncthreads();
            make_affine(g_sum[s-1][3], g_ss2[s-1][3], g3 + (s-1)*100, b3 + (s-1)*100, 100, affA, affC);
        }
        __syncthreads();
        {
            const float ec = expf(-0.3f * (1.0f - (float)s * (1.0f / 64.0f)));
            const float yold = ys[r_];
            const float* Wold = Wc + (s & 1) * WSTR + r_ * 100;
            const float* Wnew = Wc + ((s + 1) & 1) * WSTR + r_ * 100;
            float zdot = 0.f;
            for (int d = q_; d < 100; d += 8) {
                float dw = Wnew[d] - Wold[d];
                float zv = (s == 0) ? z0v : fmaf(affA[d], hB[r_ * HP + d], affC[d]) * 0.01f;
                zdot = fmaf(zv, dw, zdot);
            }
            ssin += __shfl_xor_sync(0xffffffffu, ssin, 1);
            ssin += __shfl_xor_sync(0xffffffffu, ssin, 2);
            ssin += __shfl_xor_sync(0xffffffffu, ssin, 4);
            zdot += __shfl_xor_sync(0xffffffffu, zdot, 1);
            zdot += __shfl_xor_sync(0xffffffffu, zdot, 2);
            zdot += __shfl_xor_sync(0xffffffffu, zdot, 4);
            if (q_ == 0) {
                float tc = 0.1f * ssin;
                float dr = fmaf(-0.1f, yold, 0.045f * ec * tc * tc * tc);
                ys[r_] = yold - dr * (1.0f / 64.0f) + zdot;
            }
        }
        __syncthreads();
        if (tid == 0) {             // y-stat (feature 100) + arrive stats0
            float s1 = 0.f, s2 = 0.f;
#pragma unroll 8
            for (int r = 0; r < RPB; r++) { float v = ys[r]; s1 += v; s2 = fmaf(v, v, s2); }
            int sh = bk & 7;
            atomicAdd(&g_sum[s][0][100 * FS + sh], s1);
            atomicAdd(&g_ss2[s][0][100 * FS + sh], s2);
            arrive_cnt(base + 0);
            wait_cnt(base + 0);
        }
        __syncthreads();

        // ---- Phase B: BN0 affine+apply (dup pairs), GEMM0 || load w1, dump w1 || stats1
        make_affine(g_sum[s][0], g_ss2[s][0], g0 + s*101, b0 + s*101, 101, affA, affC);
        __syncthreads();
        for (int i = tid; i < RPB * 101; i += NTH) {
            int r = i / 101, f = i % 101;
            float v = (f < 100) ? xs[r * XP + f] : ys[r];
            v = fmaf(affA[f], v, affC[f]);
            *(float2*)&hA2[r * HP2 + 2 * f] = make_float2(v, v);
        }
        __syncthreads();
        {
            float4 wreg[12];
            if (tid < 256) gemm64<101, 110>(hA2, wb, hB);
            else {
                const float4* src = (const float4*)(w1 + (size_t)s * 12100);
                int t = tid - 256;
#pragma unroll
                for (int i = 0; i < 12; i++) {
                    int idx = t + i * 256;
                    wreg[i] = (idx < 3025) ? src[idx] : make_float4(0.f, 0.f, 0.f, 0.f);
                }
            }
            __syncthreads();
            if (tid >= 256) {
                float4* dst = (float4*)wb;
                int t = tid - 256;
#pragma unroll
                for (int i = 0; i < 12; i++) {
                    int idx = t + i * 256;
                    if (idx < 3025) dst[idx] = wreg[i];
                }
            } else if (tid < 128) stats128(hB, HP, 110, g_sum[s][1], g_ss2[s][1]);
        }
        __syncthreads();
        if (tid == 0) { arrive_cnt(base + 1); wait_cnt(base + 1); }
        __syncthreads();

        // ---- Phase C: BN1+relu, GEMM1 || load w2, dump w2 || stats2
        make_affine(g_sum[s][1], g_ss2[s][1], g1 + s*110, b1 + s*110, 110, affA, affC);
        __syncthreads();
        for (int i = tid; i < RPB * 110; i += NTH) {
            int r = i / 110, f = i % 110;
            float v = fmaxf(fmaf(affA[f], hB[r * HP + f], affC[f]), 0.f);
            *(float2*)&hA2[r * HP2 + 2 * f] = make_float2(v, v);
        }
        __syncthreads();
        {
            float4 wreg[11];
            if (tid < 256) gemm64<110, 110>(hA2, wb, hB);
            else {
                const float4* src = (const float4*)(w2 + (size_t)s * 11000);
                int t = tid - 256;
#pragma unroll
                for (int i = 0; i < 11; i++) {
                    int idx = t + i * 256;
                    wreg[i] = (idx < 2750) ? src[idx] : make_float4(0.f, 0.f, 0.f, 0.f);
                }
            }
            __syncthreads();
            if (tid >= 256) {
                float4* dst = (float4*)wb;
                int t = tid - 256;
#pragma unroll
                for (int i = 0; i < 11; i++) {
                    int idx = t + i * 256;
                    if (idx < 2750) dst[idx] = wreg[i];
                }
            } else if (tid < 128) stats128(hB, HP, 110, g_sum[s][2], g_ss2[s][2]);
        }
        __syncthreads();
        if (tid == 0) { arrive_cnt(base + 2); wait_cnt(base + 2); }
        __syncthreads();

        // ---- Phase D: BN2+relu, GEMM2 || prefetch W[s+2], stats3, arrive (no wait!)
        make_affine(g_sum[s][2], g_ss2[s][2], g2 + s*110, b2 + s*110, 110, affA, affC);
        __syncthreads();
        for (int i = tid; i < RPB * 110; i += NTH) {
            int r = i / 110, f = i % 110;
            float v = fmaxf(fmaf(affA[f], hB[r * HP + f], affC[f]), 0.f);
            *(float2*)&hA2[r * HP2 + 2 * f] = make_float2(v, v);
        }
        __syncthreads();
        if (tid < 256) gemm64<110, 100>(hA2, wb, hB);
        else if (s <= 61) prefetch_W256(Wc + (s & 1) * WSTR, W, row0, s + 2);
        __syncthreads();
        if (tid < 128) stats128(hB, HP, 100, g_sum[s][3], g_ss2[s][3]);
        __syncthreads();
        if (tid == 0) arrive_cnt(base + 3);   // wait happens in next phase A
    }

    // ---- Final extra step; write outputs
    if (tid == 0) wait_cnt(62 * 4 + 3);
    __syncthreads();
    make_affine(g_sum[62][3], g_ss2[62][3], g3 + 62*100, b3 + 62*100, 100, affA, affC);
    __syncthreads();
    {
        float ec = expf(-0.3f * (1.0f - 62.0f / 64.0f));
        float yold = ys[r_];
        const float* Wold = Wc + r_ * 100;           // W[62]
        const float* Wnew = Wc + WSTR + r_ * 100;    // W[63]
        float ssin = 0.f, zdot = 0.f;
        for (int d = q_; d < 100; d += 8) {
            float dw = Wnew[d] - Wold[d];
            float xn = fmaf(0.3f * dw, yold, xs[r_ * XP + d]);
            out[(size_t)(row0 + r_) * 100 + d] = xn;
            ssin += my_sin(xn);
            float zv = fmaf(affA[d], hB[r_ * HP + d], affC[d]) * 0.01f;
            zdot = fmaf(zv, dw, zdot);
        }
        ssin += __shfl_xor_sync(0xffffffffu, ssin, 1);
        ssin += __shfl_xor_sync(0xffffffffu, ssin, 2);
        ssin += __shfl_xor_sync(0xffffffffu, ssin, 4);
        zdot += __shfl_xor_sync(0xffffffffu, zdot, 1);
        zdot += __shfl_xor_sync(0xffffffffu, zdot, 2);
        zdot += __shfl_xor_sync(0xffffffffu, zdot, 4);
        if (q_ == 0) {
            float tc = 0.1f * ssin;
            float dr = fmaf(-0.1f, yold, 0.045f * ec * tc * tc * tc);
            out[(size_t)8192 * 100 + row0 + r_] = yold - dr * (1.0f / 64.0f) + zdot;
        }
    }
}

extern "C" void kernel_launch(void* const* d_in, const int* in_sizes, int n_in,
                              void* d_out, int out_size) {
    cudaFuncSetAttribute(fullnn, cudaFuncAttributeMaxDynamicSharedMemorySize, SMEM_BYTES);
    fullnn<<<NBLK, NTH, SMEM_BYTES>>>(
        (const float*)d_in[0], (const float*)d_in[1], (const float*)d_in[2],
        (const float*)d_in[3], (const float*)d_in[4], (const float*)d_in[5],
        (const float*)d_in[6], (const float*)d_in[7], (const float*)d_in[8],
        (const float*)d_in[9], (const float*)d_in[10], (const float*)d_in[11],
        (const float*)d_in[12], (const float*)d_in[13],
        (float*)d_out);
}

// round 8
// speedup vs baseline: 1.5884x; 1.1997x over previous
#include <cuda_runtime.h>
#include <math.h>

#define NBLK 128
#define NTH  512
#define RPB  64
#define XP   104
#define HP   120
#define HP2  224
#define FS   40
#define WSTR 6400

#define OFF_XS   0
#define OFF_YS   6656
#define OFF_HA2  6720
#define OFF_HB   21056
#define OFF_WB   28736
#define OFF_AFA  40836
#define OFF_AFC  40964
#define OFF_WC   41092
#define SMEM_FLOATS 53892
#define SMEM_BYTES  (SMEM_FLOATS * 4)

__device__ __align__(16) float g_sum[63][4][128 * FS];
__device__ __align__(16) float g_ss2[63][4][128 * FS];
__device__ __align__(16) unsigned g_flags[NBLK * 32];
__device__ unsigned g_release;
__device__ __align__(16) unsigned g_arrive[256];
__device__ __align__(16) unsigned g_arriveY[64];

__device__ __forceinline__ void gridbar(unsigned gen) {
    __syncthreads();
    if (threadIdx.x == 0) {
        __threadfence();
        *(volatile unsigned*)&g_flags[blockIdx.x * 32] = gen;
    }
    if (blockIdx.x == 0) {
        if (threadIdx.x < NBLK) {
            volatile unsigned* fp = &g_flags[threadIdx.x * 32];
            while (*fp < gen) {}
        }
        __syncthreads();
        if (threadIdx.x == 0) { __threadfence(); *(volatile unsigned*)&g_release = gen; }
        __syncthreads();
    } else {
        if (threadIdx.x == 0) {
            volatile unsigned* rp = &g_release;
            while (*rp < gen) {}
            __threadfence();
        }
        __syncthreads();
    }
}

__device__ __forceinline__ void arrive_cnt(unsigned* c) { __threadfence(); atomicAdd(c, 1u); }
__device__ __forceinline__ void wait_cnt(unsigned* c) {
    volatile unsigned* p = c;
    while (*p < NBLK) {}
    __threadfence();
}

__device__ __forceinline__ void cp_async16(float* dst_smem, const float* src) {
    unsigned d = (unsigned)__cvta_generic_to_shared(dst_smem);
    asm volatile("cp.async.cg.shared.global [%0], [%1], 16;\n" :: "r"(d), "l"(src));
}
__device__ __forceinline__ void cp_commit() { asm volatile("cp.async.commit_group;\n"); }
__device__ __forceinline__ void cp_wait0()  { asm volatile("cp.async.wait_group 0;\n" ::: "memory"); }

#define FMA2(acc, a, b) asm("fma.rn.f32x2 %0, %1, %2, %0;" : "+l"(acc) : "l"(a), "l"(b))

__device__ __forceinline__ float my_sin(float x) {
    float kf = rintf(x * 0.63661977236758134f);
    int k = (int)kf;
    float r = fmaf(-kf, 1.57079637050628662f, x);
    r = fmaf(-kf, -4.37113900018624283e-8f, r);
    float r2 = r * r;
    float sp = fmaf(r2, 2.7557314e-6f, -1.9841270e-4f);
    sp = fmaf(r2, sp, 8.3333331e-3f);
    sp = fmaf(r2, sp, -1.6666667e-1f);
    sp = r * fmaf(r2, sp, 1.0f);
    float cp = fmaf(r2, 2.4801587e-5f, -1.3888889e-3f);
    cp = fmaf(r2, cp, 4.1666666e-2f);
    cp = fmaf(r2, cp, -0.5f);
    cp = fmaf(r2, cp, 1.0f);
    int kk = k & 3;
    float res = (kk & 1) ? cp : sp;
    if (kk >= 2) res = -res;
    return res;
}

// compute affine for feature f from shards (callable per-thread)
__device__ __forceinline__ void affine_one(const float* gs, const float* gq,
                                           float gamma, float beta, int f,
                                           float* a_out, float* c_out) {
    float4 a0 = __ldcg((const float4*)&gs[f * FS]);
    float4 a1 = __ldcg((const float4*)&gs[f * FS + 4]);
    float4 b0 = __ldcg((const float4*)&gq[f * FS]);
    float4 b1 = __ldcg((const float4*)&gq[f * FS + 4]);
    float mu  = (((a0.x + a0.y) + (a0.z + a0.w)) + ((a1.x + a1.y) + (a1.z + a1.w))) * (1.f / 8192.f);
    float ex2 = (((b0.x + b0.y) + (b0.z + b0.w)) + ((b1.x + b1.y) + (b1.z + b1.w))) * (1.f / 8192.f);
    float v = fmaxf(ex2 - mu * mu, 0.f) + 1e-6f;
    float rs = rsqrtf(v);
    rs = rs * (1.5f - 0.5f * v * rs * rs);
    float a = gamma * rs;
    *a_out = a;
    *c_out = fmaf(-a, mu, beta);
}

__device__ __forceinline__ void make_affine(const float* gs, const float* gq,
                                            const float* __restrict__ gamma,
                                            const float* __restrict__ beta,
                                            int nf, float* affA, float* affC) {
    int f = threadIdx.x;
    if (f < nf) {
        float a, c;
        affine_one(gs, gq, gamma[f], beta[f], f, &a, &c);
        affA[f] = a; affC[f] = c;
    }
}

__device__ __forceinline__ void stats128(const float* buf, int pitch, int nf,
                                         float* gs, float* gq) {
    int f = threadIdx.x;
    if (f < nf) {
        float s1 = 0.f, s2 = 0.f;
        const float* p = buf + f;
#pragma unroll 8
        for (int r = 0; r < RPB; r++) { float v = p[r * pitch]; s1 += v; s2 = fmaf(v, v, s2); }
        int sh = blockIdx.x & 7;
        atomicAdd(&gs[f * FS + sh], s1);
        atomicAdd(&gq[f * FS + sh], s2);
    }
}

// FFMA2 GEMM pieces. tid<256. acc persists across main/tail.
__device__ __forceinline__ void gemm_k(unsigned long long acc[4][4],
                                       const float* __restrict__ A,
                                       const float* __restrict__ wrow,
                                       int r0, int cg, int k) {
    const unsigned long long* a0 = (const unsigned long long*)(A + r0 * HP2);
    unsigned long long X0 = a0[k];
    unsigned long long X1 = ((const unsigned long long*)(A + (r0 + 1) * HP2))[k];
    unsigned long long X2 = ((const unsigned long long*)(A + (r0 + 2) * HP2))[k];
    unsigned long long X3 = ((const unsigned long long*)(A + (r0 + 3) * HP2))[k];
    const unsigned long long* wr = (const unsigned long long*)wrow + cg;
#pragma unroll
    for (int v = 0; v < 4; v++) {
        unsigned long long wv = wr[v * 16];
        FMA2(acc[0][v], X0, wv);
        FMA2(acc[1][v], X1, wv);
        FMA2(acc[2][v], X2, wv);
        FMA2(acc[3][v], X3, wv);
    }
}

template<int K, int NC>
__device__ __forceinline__ void gemm_main(unsigned long long acc[4][4],
                                          const float* __restrict__ A,
                                          const float* __restrict__ wm) {
    int rg = threadIdx.x >> 4, cg = threadIdx.x & 15;
    int r0 = rg * 4;
#pragma unroll 2
    for (int k = 0; k < K; k++)
        gemm_k(acc, A, wm + k * NC, r0, cg, k);
}

template<int NC>
__device__ __forceinline__ void gemm_store(unsigned long long acc[4][4],
                                           float* __restrict__ dst) {
    int rg = threadIdx.x >> 4, cg = threadIdx.x & 15;
    int r0 = rg * 4;
#pragma unroll
    for (int v = 0; v < 4; v++) {
        int j = cg * 2 + v * 32;
        if (j + 1 < NC) {
#pragma unroll
            for (int i = 0; i < 4; i++)
                *(float2*)&dst[(r0 + i) * HP + j] = *(float2*)&acc[i][v];
        }
    }
}

template<int K, int NC>
__device__ __forceinline__ void gemm64(const float* __restrict__ A,
                                       const float* __restrict__ wm,
                                       float* __restrict__ dst) {
    unsigned long long acc[4][4] = {};
    gemm_main<K, NC>(acc, A, wm);
    gemm_store<NC>(acc, dst);
}

__device__ __forceinline__ void prefetch_W256(float* Wcbuf, const float* W, int row0, int t0) {
    int t = threadIdx.x - 256;
    for (int i = t; i < RPB * 25; i += 256) {
        int r = i & 63, c = i >> 6;
        cp_async16(Wcbuf + r * 100 + c * 4,
                   W + ((size_t)(row0 + r) * 64 + t0) * 100 + c * 4);
    }
    cp_commit();
}

__global__ void __launch_bounds__(NTH, 1)
fullnn(const float* __restrict__ W,
       const float* __restrict__ y_init, const float* __restrict__ z_init,
       const float* __restrict__ g0, const float* __restrict__ b0,
       const float* __restrict__ g1, const float* __restrict__ b1,
       const float* __restrict__ g2, const float* __restrict__ b2,
       const float* __restrict__ g3, const float* __restrict__ b3,
       const float* __restrict__ w0, const float* __restrict__ w1,
       const float* __restrict__ w2,
       float* __restrict__ out)
{
    extern __shared__ float sm[];
    float* xs   = sm + OFF_XS;
    float* ys   = sm + OFF_YS;
    float* hA2  = sm + OFF_HA2;
    float* hB   = sm + OFF_HB;
    float* wb   = sm + OFF_WB;
    float* affA = sm + OFF_AFA;
    float* affC = sm + OFF_AFC;
    float* Wc   = sm + OFF_WC;

    const int tid  = threadIdx.x;
    const int bk   = blockIdx.x;
    const int row0 = bk * RPB;
    const int r_ = tid >> 3, q_ = tid & 7;
    const int fA = tid & 127, rbA = tid >> 7;     // de-div apply indices

    unsigned gen = *(volatile unsigned*)&g_release;

    for (int i = tid; i < RPB * 25; i += NTH) {
        int r = i & 63, c = i >> 6;
        cp_async16(Wc + r * 100 + c * 4, W + ((size_t)(row0 + r) * 64 + 0) * 100 + c * 4);
        cp_async16(Wc + WSTR + r * 100 + c * 4, W + ((size_t)(row0 + r) * 64 + 1) * 100 + c * 4);
    }
    cp_commit();

    {   // zero stats + counters
        float4* p1 = (float4*)&g_sum[0][0][0];
        float4* p2 = (float4*)&g_ss2[0][0][0];
        int n4 = 63 * 4 * 128 * FS / 4;
        for (int i = bk * NTH + tid; i < n4; i += NBLK * NTH) {
            p1[i] = make_float4(0.f, 0.f, 0.f, 0.f);
            p2[i] = make_float4(0.f, 0.f, 0.f, 0.f);
        }
        if (bk == 0) {
            if (tid < 256) g_arrive[tid] = 0u;
            if (tid < 64)  g_arriveY[tid] = 0u;
        }
    }
    const float y0v = y_init[0];
    const float z0v = z_init[0];
    for (int i = tid; i < RPB * 100; i += NTH) {
        int r = i / 100, d = i - r * 100;
        xs[r * XP + d] = 1.57079632679489662f;
    }
    for (int r = tid; r < RPB; r += NTH) ys[r] = y0v;
    cp_wait0();
    gridbar(++gen);

    for (int s = 0; s < 63; s++) {
        const int base = s * 4;
        // ---- 1: x update + sin (no global deps)
        cp_wait0();
        __syncthreads();
        float ssin = 0.f;
        {
            const float yold = ys[r_];
            const float* Wold = Wc + (s & 1) * WSTR + r_ * 100;
            const float* Wnew = Wc + ((s + 1) & 1) * WSTR + r_ * 100;
#pragma unroll 13
            for (int d = q_; d < 100; d += 8) {
                float dw = Wnew[d] - Wold[d];
                float xn = fmaf(0.3f * dw, yold, xs[r_ * XP + d]);
                xs[r_ * XP + d] = xn;
                ssin += my_sin(xn);
            }
        }
        __syncthreads();
        // ---- 2: push x-stats early || stage w0
        if (tid < 100) {
            float s1 = 0.f, s2 = 0.f;
            const float* p = xs + tid;
#pragma unroll 8
            for (int r = 0; r < RPB; r++) { float v = p[r * XP]; s1 += v; s2 = fmaf(v, v, s2); }
            int sh = bk & 7;
            atomicAdd(&g_sum[s][0][tid * FS + sh], s1);
            atomicAdd(&g_ss2[s][0][tid * FS + sh], s2);
        } else if (tid >= 128) {
            const float2* src = (const float2*)(w0 + (size_t)s * 11110);
            float2* dst = (float2*)wb;
            for (int i = tid - 128; i < 5555; i += 384) dst[i] = src[i];
        }
        __syncthreads();
        if (tid == 0) arrive_cnt(&g_arrive[base + 0]);
        // ---- 3: wait stats3(s-1), BN3 affine
        if (s > 0) {
            if (tid == 0) wait_cnt(&g_arrive[base - 1]);
            __syncthreads();
            make_affine(g_sum[s-1][3], g_ss2[s-1][3], g3 + (s-1)*100, b3 + (s-1)*100, 100, affA, affC);
        }
        __syncthreads();
        // ---- 4: zdot + y update
        {
            const float ec = expf(-0.3f * (1.0f - (float)s * (1.0f / 64.0f)));
            const float yold = ys[r_];
            const float* Wold = Wc + (s & 1) * WSTR + r_ * 100;
            const float* Wnew = Wc + ((s + 1) & 1) * WSTR + r_ * 100;
            float zdot = 0.f;
#pragma unroll 13
            for (int d = q_; d < 100; d += 8) {
                float dw = Wnew[d] - Wold[d];
                float zv = (s == 0) ? z0v : fmaf(affA[d], hB[r_ * HP + d], affC[d]) * 0.01f;
                zdot = fmaf(zv, dw, zdot);
            }
            ssin += __shfl_xor_sync(0xffffffffu, ssin, 1);
            ssin += __shfl_xor_sync(0xffffffffu, ssin, 2);
            ssin += __shfl_xor_sync(0xffffffffu, ssin, 4);
            zdot += __shfl_xor_sync(0xffffffffu, zdot, 1);
            zdot += __shfl_xor_sync(0xffffffffu, zdot, 2);
            zdot += __shfl_xor_sync(0xffffffffu, zdot, 4);
            if (q_ == 0) {
                float tc = 0.1f * ssin;
                float dr = fmaf(-0.1f, yold, 0.045f * ec * tc * tc * tc);
                ys[r_] = yold - dr * (1.0f / 64.0f) + zdot;
            }
        }
        __syncthreads();
        // ---- 5: warp1 y-stat + arriveY ; tid0 waits x-stats
        if (tid >= 32 && tid < 64) {
            int l = tid - 32;
            float v0 = ys[2 * l], v1 = ys[2 * l + 1];
            float s1 = v0 + v1;
            float s2 = fmaf(v0, v0, v1 * v1);
            for (int o = 16; o > 0; o >>= 1) {
                s1 += __shfl_xor_sync(0xffffffffu, s1, o);
                s2 += __shfl_xor_sync(0xffffffffu, s2, o);
            }
            if (l == 0) {
                int sh = bk & 7;
                atomicAdd(&g_sum[s][0][100 * FS + sh], s1);
                atomicAdd(&g_ss2[s][0][100 * FS + sh], s2);
                arrive_cnt(&g_arriveY[s]);
            }
        }
        if (tid == 0) wait_cnt(&g_arrive[base + 0]);
        __syncthreads();
        // ---- 6: BN0 affine (x features) + apply x cols as dup pairs
        make_affine(g_sum[s][0], g_ss2[s][0], g0 + s*101, b0 + s*101, 100, affA, affC);
        __syncthreads();
        if (fA < 100) {
            float a = affA[fA], c = affC[fA];
#pragma unroll
            for (int i = 0; i < 16; i++) {
                int r = rbA + 4 * i;
                float v = fmaf(a, xs[r * XP + fA], c);
                *(float2*)&hA2[r * HP2 + 2 * fA] = make_float2(v, v);
            }
        }
        __syncthreads();
        // ---- 7: GEMM0 main (k<100) || y-path waits+applies col 100
        unsigned long long acc[4][4] = {};
        if (tid < 256) {
            gemm_main<100, 110>(acc, hA2, wb);
        } else if (tid < 320) {
            int t = tid - 256;
            if (t == 0) wait_cnt(&g_arriveY[s]);
            // all 64 threads poll cheaply then proceed
            volatile unsigned* p = &g_arriveY[s];
            while (*p < NBLK) {}
            __threadfence();
            float a, c;
            affine_one(g_sum[s][0], g_ss2[s][0], g0[s*101 + 100], b0[s*101 + 100], 100, &a, &c);
            float v = fmaf(a, ys[t], c);
            *(float2*)&hA2[t * HP2 + 200] = make_float2(v, v);
        }
        __syncthreads();
        // ---- 8: GEMM0 tail k=100 + store
        if (tid < 256) {
            gemm_k(acc, hA2, wb + 100 * 110, (tid >> 4) * 4, tid & 15, 100);
            gemm_store<110>(acc, hB);
        }
        __syncthreads();
        // ---- 9: stats1 || copy w1 into wb
        if (tid < 128) stats128(hB, HP, 110, g_sum[s][1], g_ss2[s][1]);
        else if (tid >= 256) {
            const float4* src = (const float4*)(w1 + (size_t)s * 12100);
            float4* dst = (float4*)wb;
#pragma unroll
            for (int i = 0; i < 12; i++) {
                int idx = (tid - 256) + i * 256;
                if (idx < 3025) dst[idx] = src[idx];
            }
        }
        __syncthreads();
        if (tid == 0) { arrive_cnt(&g_arrive[base + 1]); wait_cnt(&g_arrive[base + 1]); }
        __syncthreads();
        // ---- Phase C: BN1+relu, GEMM1, stats2 || copy w2
        make_affine(g_sum[s][1], g_ss2[s][1], g1 + s*110, b1 + s*110, 110, affA, affC);
        __syncthreads();
        if (fA < 110) {
            float a = affA[fA], c = affC[fA];
#pragma unroll
            for (int i = 0; i < 16; i++) {
                int r = rbA + 4 * i;
                float v = fmaxf(fmaf(a, hB[r * HP + fA], c), 0.f);
                *(float2*)&hA2[r * HP2 + 2 * fA] = make_float2(v, v);
            }
        }
        __syncthreads();
        if (tid < 256) gemm64<110, 110>(hA2, wb, hB);
        __syncthreads();
        if (tid < 128) stats128(hB, HP, 110, g_sum[s][2], g_ss2[s][2]);
        else if (tid >= 256) {
            const float4* src = (const float4*)(w2 + (size_t)s * 11000);
            float4* dst = (float4*)wb;
#pragma unroll
            for (int i = 0; i < 11; i++) {
                int idx = (tid - 256) + i * 256;
                if (idx < 2750) dst[idx] = src[idx];
            }
        }
        __syncthreads();
        if (tid == 0) { arrive_cnt(&g_arrive[base + 2]); wait_cnt(&g_arrive[base + 2]); }
        __syncthreads();
        // ---- Phase D: BN2+relu, GEMM2 || prefetch W, stats3, arrive (no wait)
        make_affine(g_sum[s][2], g_ss2[s][2], g2 + s*110, b2 + s*110, 110, affA, affC);
        __syncthreads();
        if (fA < 110) {
            float a = affA[fA], c = affC[fA];
#pragma unroll
            for (int i = 0; i < 16; i++) {
                int r = rbA + 4 * i;
                float v = fmaxf(fmaf(a, hB[r * HP + fA], c), 0.f);
                *(float2*)&hA2[r * HP2 + 2 * fA] = make_float2(v, v);
            }
        }
        __syncthreads();
        if (tid < 256) gemm64<110, 100>(hA2, wb, hB);
        else if (s <= 61) prefetch_W256(Wc + (s & 1) * WSTR, W, row0, s + 2);
        __syncthreads();
        if (tid < 128) stats128(hB, HP, 100, g_sum[s][3], g_ss2[s][3]);
        __syncthreads();
        if (tid == 0) arrive_cnt(&g_arrive[base + 3]);
    }

    // ---- Final extra step; write outputs
    if (tid == 0) wait_cnt(&g_arrive[62 * 4 + 3]);
    __syncthreads();
    make_affine(g_sum[62][3], g_ss2[62][3], g3 + 62*100, b3 + 62*100, 100, affA, affC);
    __syncthreads();
    {
        float ec = expf(-0.3f * (1.0f - 62.0f / 64.0f));
        float yold = ys[r_];
        const float* Wold = Wc + r_ * 100;
        const float* Wnew = Wc + WSTR + r_ * 100;
        float ssin = 0.f, zdot = 0.f;
        for (int d = q_; d < 100; d += 8) {
            float dw = Wnew[d] - Wold[d];
            float xn = fmaf(0.3f * dw, yold, xs[r_ * XP + d]);
            out[(size_t)(row0 + r_) * 100 + d] = xn;
            ssin += my_sin(xn);
            float zv = fmaf(affA[d], hB[r_ * HP + d], affC[d]) * 0.01f;
            zdot = fmaf(zv, dw, zdot);
        }
        ssin += __shfl_xor_sync(0xffffffffu, ssin, 1);
        ssin += __shfl_xor_sync(0xffffffffu, ssin, 2);
        ssin += __shfl_xor_sync(0xffffffffu, ssin, 4);
        zdot += __shfl_xor_sync(0xffffffffu, zdot, 1);
        zdot += __shfl_xor_sync(0xffffffffu, zdot, 2);
        zdot += __shfl_xor_sync(0xffffffffu, zdot, 4);
        if (q_ == 0) {
            float tc = 0.1f * ssin;
            float dr = fmaf(-0.1f, yold, 0.045f * ec * tc * tc * tc);
            out[(size_t)8192 * 100 + row0 + r_] = yold - dr * (1.0f / 64.0f) + zdot;
        }
    }
}

extern "C" void kernel_launch(void* const* d_in, const int* in_sizes, int n_in,
                              void* d_out, int out_size) {
    cudaFuncSetAttribute(fullnn, cudaFuncAttributeMaxDynamicSharedMemorySize, SMEM_BYTES);
    fullnn<<<NBLK, NTH, SMEM_BYTES>>>(
        (const float*)d_in[0], (const float*)d_in[1], (const float*)d_in[2],
        (const float*)d_in[3], (const float*)d_in[4], (const float*)d_in[5],
        (const float*)d_in[6], (const float*)d_in[7], (const float*)d_in[8],
        (const float*)d_in[9], (const float*)d_in[10], (const float*)d_in[11],
        (const float*)d_in[12], (const float*)d_in[13],
        (float*)d_out);
}